// round 14
// baseline (speedup 1.0000x reference)
#include <cuda_runtime.h>
#include <cuda_fp16.h>
#include <cuda_bf16.h>
#include <math.h>

#define NN      50000
#define INDIM   512
#define HID     256
#define CC      8
#define E2C     400000
#define EEC     800000
#define T_ITERS 10
#define ETA_C   0.2f
#define W_MAXC  0.8f
#define ALPHA_MAXC 1.5f
#define EPS_C   1e-12f

// ------------------- scratch (device globals; no allocation allowed) ---------
__device__ __align__(16) float g_h[NN * HID];            // 51.2 MB (fp32, logits)
__device__ __align__(16) __nv_bfloat162 g_hb[NN * HID / 2]; // 25.6 MB (bf16, edge MLP)
__device__ __align__(16) float g_logphi[NN * CC];
__device__ __align__(16) float g_deg[NN];
__device__ __align__(16) float g_w[E2C];
__device__ __align__(16) float g_en[E2C];
__device__ __align__(16) __half2 g_m[EEC * 4];       // 12.8 MB (fp16)
__device__ __align__(16) float g_sumA[NN * CC];
__device__ __align__(16) float g_sumB[NN * CC];
__device__ __align__(16) __half2 g_b16[NN * 4];      // fp16 b = lp + alpha*sum
__device__ __align__(16) float g_Rs[64];
__device__ float g_alpha;

// ------------------- bf16 pack helpers ----------------------------------------
__device__ __forceinline__ unsigned pack_bf16(__nv_bfloat16 lo, __nv_bfloat16 hi) {
    return ((unsigned)__bfloat16_as_ushort(hi) << 16) | __bfloat16_as_ushort(lo);
}
__device__ __forceinline__ unsigned pack_bf16f(float lo, float hi) {
    __nv_bfloat162 t = __floats2bfloat162_rn(lo, hi);
    return *(unsigned*)&t;
}
__device__ __forceinline__ __nv_bfloat162 u2bf(unsigned x) {
    __nv_bfloat162 r; *(unsigned*)&r = x; return r;
}
__device__ __forceinline__ unsigned bf2u(__nv_bfloat162 x) {
    return *(unsigned*)&x;
}

#define MMA_BF16(accp, a0, a1, a2, a3, b0, b1) \
    asm("mma.sync.aligned.m16n8k16.row.col.f32.bf16.bf16.f32 " \
        "{%0,%1,%2,%3}, {%4,%5,%6,%7}, {%8,%9}, {%0,%1,%2,%3};" \
        : "+f"((accp)[0]), "+f"((accp)[1]), "+f"((accp)[2]), "+f"((accp)[3]) \
        : "r"(a0), "r"(a1), "r"(a2), "r"(a3), "r"(b0), "r"(b1))

// ------------------- vector reduction (atomic add, no return) -----------------
__device__ __forceinline__ void red4(float* p, float a, float b, float c, float d) {
    asm volatile("red.global.add.v4.f32 [%0], {%1, %2, %3, %4};"
                 :: "l"(p), "f"(a), "f"(b), "f"(c), "f"(d) : "memory");
}

// ------------------- generic zero --------------------------------------------
__global__ void zero4_k(float4* __restrict__ p, int n4) {
    int i = blockIdx.x * blockDim.x + threadIdx.x;
    if (i < n4) p[i] = make_float4(0.f, 0.f, 0.f, 0.f);
}

// ------------------- prep: zero deg + symmetrized R + alpha -------------------
__global__ void prep0_k(const float* __restrict__ R_raw,
                        const float* __restrict__ rsl,
                        const float* __restrict__ msg) {
    int i = blockIdx.x * blockDim.x + threadIdx.x;
    if (i < NN) g_deg[i] = 0.f;
    if (blockIdx.x == 0) {
        int t = threadIdx.x;
        if (t == 0) g_alpha = ALPHA_MAXC / (1.f + expf(-msg[0]));
        if (t < 64) {
            int c = t >> 3, d = t & 7;
            float r = 0.5f * (R_raw[c * 8 + d] + R_raw[d * 8 + c]);
            float xr = rsl[0];
            float sp = (xr > 20.f) ? xr : log1pf(expf(xr));
            g_Rs[t] = (sp + 1e-6f) * tanhf(r);
        }
    }
}

// ------------------- encoder GEMM via split-bf16 mma.sync ---------------------
__global__ __launch_bounds__(256, 3) void enc_gemm_k(const float* __restrict__ X,
                                                     const float* __restrict__ W,
                                                     const float* __restrict__ B) {
    __shared__ unsigned Ahi[128][20], Alo[128][20];   // bf16x2 pairs (16/row) pad 20
    __shared__ unsigned Bpk[2][2][8][68];             // [mat][s][rp][n] pad 68

    int tid  = threadIdx.x;
    int wid  = tid >> 5;
    int lane = tid & 31;
    int gid  = lane >> 2;
    int tg   = lane & 3;
    int warp_m = wid & 3;          // 4 x 32 rows
    int warp_n = wid >> 2;         // 2 x 32 cols
    int row0 = blockIdx.x * 128;
    int col0 = blockIdx.y * 64;

    float acc[2][4][4];
#pragma unroll
    for (int mt = 0; mt < 2; mt++)
#pragma unroll
        for (int nt = 0; nt < 4; nt++)
#pragma unroll
            for (int r = 0; r < 4; r++) acc[mt][nt][r] = 0.f;

    for (int f0 = 0; f0 < INDIM; f0 += 32) {
        // ---- stage A: 128 rows x 32 k, hi/lo split, pair-packed ----
#pragma unroll
        for (int i = 0; i < 4; i++) {
            int idx = tid + i * 256;
            int row = idx >> 3;
            int f4  = idx & 7;
            int gr = row0 + row;
            float4 v = make_float4(0.f, 0.f, 0.f, 0.f);
            if (gr < NN) v = *(const float4*)(X + (size_t)gr * INDIM + f0 + f4 * 4);
            __nv_bfloat16 hx = __float2bfloat16(v.x);
            __nv_bfloat16 hy = __float2bfloat16(v.y);
            __nv_bfloat16 hz = __float2bfloat16(v.z);
            __nv_bfloat16 hw = __float2bfloat16(v.w);
            Ahi[row][f4 * 2]     = pack_bf16(hx, hy);
            Ahi[row][f4 * 2 + 1] = pack_bf16(hz, hw);
            Alo[row][f4 * 2]     = pack_bf16f(v.x - __bfloat162float(hx),
                                              v.y - __bfloat162float(hy));
            Alo[row][f4 * 2 + 1] = pack_bf16f(v.z - __bfloat162float(hz),
                                              v.w - __bfloat162float(hw));
        }
        // ---- stage B: 32 k rows x 64 cols of W, hi/lo, pair-packed ----
        {
            int s  = tid >> 7;             // 0..1 (k16 step)
            int rp = (tid >> 4) & 7;       // 0..7 = 2*tg + half
            int n0 = (tid & 15) * 4;
            int k0 = f0 + s * 16 + (rp & 1) * 8 + (rp >> 1) * 2;
            float4 w0 = *(const float4*)(W + (size_t)k0 * HID + col0 + n0);
            float4 w1 = *(const float4*)(W + (size_t)(k0 + 1) * HID + col0 + n0);
            __nv_bfloat16 h00 = __float2bfloat16(w0.x), h10 = __float2bfloat16(w1.x);
            __nv_bfloat16 h01 = __float2bfloat16(w0.y), h11 = __float2bfloat16(w1.y);
            __nv_bfloat16 h02 = __float2bfloat16(w0.z), h12 = __float2bfloat16(w1.z);
            __nv_bfloat16 h03 = __float2bfloat16(w0.w), h13 = __float2bfloat16(w1.w);
            Bpk[0][s][rp][n0 + 0] = pack_bf16(h00, h10);
            Bpk[0][s][rp][n0 + 1] = pack_bf16(h01, h11);
            Bpk[0][s][rp][n0 + 2] = pack_bf16(h02, h12);
            Bpk[0][s][rp][n0 + 3] = pack_bf16(h03, h13);
            Bpk[1][s][rp][n0 + 0] = pack_bf16f(w0.x - __bfloat162float(h00),
                                               w1.x - __bfloat162float(h10));
            Bpk[1][s][rp][n0 + 1] = pack_bf16f(w0.y - __bfloat162float(h01),
                                               w1.y - __bfloat162float(h11));
            Bpk[1][s][rp][n0 + 2] = pack_bf16f(w0.z - __bfloat162float(h02),
                                               w1.z - __bfloat162float(h12));
            Bpk[1][s][rp][n0 + 3] = pack_bf16f(w0.w - __bfloat162float(h03),
                                               w1.w - __bfloat162float(h13));
        }
        __syncthreads();

        // ---- compute: 2 k16 steps ----
#pragma unroll
        for (int s = 0; s < 2; s++) {
            unsigned bh[4][2], bl[4][2];
#pragma unroll
            for (int nt = 0; nt < 4; nt++) {
                int n = warp_n * 32 + nt * 8 + gid;
                bh[nt][0] = Bpk[0][s][2 * tg][n];
                bh[nt][1] = Bpk[0][s][2 * tg + 1][n];
                bl[nt][0] = Bpk[1][s][2 * tg][n];
                bl[nt][1] = Bpk[1][s][2 * tg + 1][n];
            }
#pragma unroll
            for (int mt = 0; mt < 2; mt++) {
                int m = warp_m * 32 + mt * 16;
                unsigned ah0 = Ahi[m + gid][s * 8 + tg];
                unsigned ah1 = Ahi[m + 8 + gid][s * 8 + tg];
                unsigned ah2 = Ahi[m + gid][s * 8 + 4 + tg];
                unsigned ah3 = Ahi[m + 8 + gid][s * 8 + 4 + tg];
                unsigned al0 = Alo[m + gid][s * 8 + tg];
                unsigned al1 = Alo[m + 8 + gid][s * 8 + tg];
                unsigned al2 = Alo[m + gid][s * 8 + 4 + tg];
                unsigned al3 = Alo[m + 8 + gid][s * 8 + 4 + tg];
#pragma unroll
                for (int nt = 0; nt < 4; nt++) {
                    MMA_BF16(acc[mt][nt], ah0, ah1, ah2, ah3, bh[nt][0], bh[nt][1]);
                    MMA_BF16(acc[mt][nt], ah0, ah1, ah2, ah3, bl[nt][0], bl[nt][1]);
                    MMA_BF16(acc[mt][nt], al0, al1, al2, al3, bh[nt][0], bh[nt][1]);
                }
            }
        }
        __syncthreads();
    }

    // ---- epilogue: bias + relu, fp32 + bf16 stores ----
#pragma unroll
    for (int mt = 0; mt < 2; mt++) {
#pragma unroll
        for (int nt = 0; nt < 4; nt++) {
            int col = col0 + warp_n * 32 + nt * 8 + 2 * tg;
            float2 bv = *(const float2*)(B + col);
            int r0 = row0 + warp_m * 32 + mt * 16 + gid;
            if (r0 < NN) {
                float2 o;
                o.x = fmaxf(acc[mt][nt][0] + bv.x, 0.f);
                o.y = fmaxf(acc[mt][nt][1] + bv.y, 0.f);
                *(float2*)(g_h + (size_t)r0 * HID + col) = o;
                g_hb[((size_t)r0 * HID + col) >> 1] = __floats2bfloat162_rn(o.x, o.y);
            }
            int r1 = r0 + 8;
            if (r1 < NN) {
                float2 o;
                o.x = fmaxf(acc[mt][nt][2] + bv.x, 0.f);
                o.y = fmaxf(acc[mt][nt][3] + bv.y, 0.f);
                *(float2*)(g_h + (size_t)r1 * HID + col) = o;
                g_hb[((size_t)r1 * HID + col) >> 1] = __floats2bfloat162_rn(o.x, o.y);
            }
        }
    }
}

// ------------------- logits + log_softmax: one warp per node ------------------
__global__ void logits_k(const float* __restrict__ W2, const float* __restrict__ B2) {
    int gt = blockIdx.x * blockDim.x + threadIdx.x;
    int node = gt >> 5, lane = gt & 31;
    if (node >= NN) return;
    const float* hrow = g_h + (size_t)node * HID;
    float acc[8];
#pragma unroll
    for (int c = 0; c < 8; c++) acc[c] = 0.f;
    for (int j = lane; j < HID; j += 32) {
        float hv = hrow[j];
        float4 wA = *(const float4*)(W2 + j * 8);
        float4 wB = *(const float4*)(W2 + j * 8 + 4);
        acc[0] += hv * wA.x; acc[1] += hv * wA.y;
        acc[2] += hv * wA.z; acc[3] += hv * wA.w;
        acc[4] += hv * wB.x; acc[5] += hv * wB.y;
        acc[6] += hv * wB.z; acc[7] += hv * wB.w;
    }
#pragma unroll
    for (int c = 0; c < 8; c++)
#pragma unroll
        for (int off = 16; off; off >>= 1)
            acc[c] += __shfl_xor_sync(0xffffffffu, acc[c], off);
    if (lane == 0) {
        float lg[8], mx = -1e30f;
#pragma unroll
        for (int c = 0; c < 8; c++) { lg[c] = acc[c] + B2[c]; mx = fmaxf(mx, lg[c]); }
        float s = 0.f;
#pragma unroll
        for (int c = 0; c < 8; c++) s += expf(lg[c] - mx);
        float lse = mx + logf(s);
        *(float4*)(g_logphi + node * 8)     = make_float4(lg[0]-lse, lg[1]-lse, lg[2]-lse, lg[3]-lse);
        *(float4*)(g_logphi + node * 8 + 4) = make_float4(lg[4]-lse, lg[5]-lse, lg[6]-lse, lg[7]-lse);
    }
}

// ------------------- degrees -------------------------------------------------
__global__ void deg_k(const int* __restrict__ src, const int* __restrict__ dst) {
    int e = blockIdx.x * blockDim.x + threadIdx.x;
    if (e >= E2C) return;
    atomicAdd(&g_deg[src[e]], 1.f);
    atomicAdd(&g_deg[dst[e]], 1.f);
}

// ------------------- edge MLP via bf16 mma.sync (m16n8k16) --------------------
__global__ __launch_bounds__(256, 3) void edge_mlp_k(const int* __restrict__ src,
                                                     const int* __restrict__ dst,
                                                     const float* __restrict__ W1,
                                                     const float* __restrict__ B1,
                                                     const float* __restrict__ W2,
                                                     const float* __restrict__ B2) {
    __shared__ int   ss[128], dd[128];
    __shared__ float s0s[128], s1s[128];
    __shared__ unsigned Hsp[128][20], Hdp[128][20];  // bf16x2 pairs, 16/row, pad 20
    __shared__ unsigned Bw[2][2][8][72];             // [part][s][rp][n] bf16x2 pairs
    __shared__ float Wg0[64], Wg1[64], b1s[64], w2s[64];
    __shared__ float wsum[128];

    int tid  = threadIdx.x;
    int wid  = tid >> 5;
    int lane = tid & 31;
    int gid  = lane >> 2;      // group id 0..7
    int tg   = lane & 3;       // thread-in-group 0..3
    int warp_m = wid & 3;      // 4 m-warps * 32 edges
    int warp_n = wid >> 2;     // 2 n-warps * 32 cols
    int e0 = blockIdx.x * 128;

    if (tid < 128) {
        int ge = e0 + tid;
        int s = src[ge], d = dst[ge];
        ss[tid] = s; dd[tid] = d;
        float degs = g_deg[s], degd = g_deg[d];
        float a = logf(degs + 1.f), b = logf(degd + 1.f);
        s0s[tid] = a + b; s1s[tid] = fabsf(a - b);
        float ds = fmaxf(degs, 1.f), dd2 = fmaxf(degd, 1.f);
        g_en[ge] = rsqrtf(ds * dd2);
        wsum[tid] = 0.f;
    } else {
        int t = tid - 128;
        if (t < 64) { Wg0[t] = W1[512 * 64 + t]; b1s[t] = B1[t]; }
        else { int u = t - 64; Wg1[u] = W1[513 * 64 + u]; w2s[u] = W2[u]; }
    }
    __syncthreads();

    float acc[2][4][4];
#pragma unroll
    for (int mt = 0; mt < 2; mt++)
#pragma unroll
        for (int nt = 0; nt < 4; nt++)
#pragma unroll
            for (int r = 0; r < 4; r++) acc[mt][nt][r] = 0.f;

    for (int f0 = 0; f0 < HID; f0 += 32) {
        // ---- stage A: raw bf16x2 copies of hs/hd rows (no conversion) ----
        {
            int e = tid >> 1;
            int half = tid & 1;
            const uint4* hs4 = (const uint4*)(g_hb + (((size_t)ss[e] * HID + f0) >> 1) + half * 8);
            const uint4* hd4 = (const uint4*)(g_hb + (((size_t)dd[e] * HID + f0) >> 1) + half * 8);
#pragma unroll
            for (int j = 0; j < 2; j++) {
                *(uint4*)&Hsp[e][half * 8 + j * 4] = hs4[j];
                *(uint4*)&Hdp[e][half * 8 + j * 4] = hd4[j];
            }
        }
        // ---- stage B: weight k-pairs as bf16x2, both parts ----
        {
            int part = tid >> 7;           // 0..1
            int s    = (tid >> 6) & 1;     // 0..1
            int rp   = (tid >> 3) & 7;     // 0..7: (rp>>2)=khalf, (rp&3)=tg
            int n0   = (tid & 7) * 8;
            int rk = (part ? 256 : 0) + f0 + s * 16 + (rp >> 2) * 8 + (rp & 3) * 2;
            const float* Wp = W1 + (size_t)rk * 64 + n0;
            float4 w0a = *(const float4*)(Wp);
            float4 w0b = *(const float4*)(Wp + 4);
            float4 w1a = *(const float4*)(Wp + 64);
            float4 w1b = *(const float4*)(Wp + 68);
            unsigned* o = &Bw[part][s][rp][n0];
            o[0] = pack_bf16f(w0a.x, w1a.x);
            o[1] = pack_bf16f(w0a.y, w1a.y);
            o[2] = pack_bf16f(w0a.z, w1a.z);
            o[3] = pack_bf16f(w0a.w, w1a.w);
            o[4] = pack_bf16f(w0b.x, w1b.x);
            o[5] = pack_bf16f(w0b.y, w1b.y);
            o[6] = pack_bf16f(w0b.z, w1b.z);
            o[7] = pack_bf16f(w0b.w, w1b.w);
        }
        __syncthreads();

        // ---- compute: 2 k16 steps; P/Q built from one hs/hd load set ----
#pragma unroll
        for (int s = 0; s < 2; s++) {
            unsigned bP[4][2], bQ[4][2];
#pragma unroll
            for (int nt = 0; nt < 4; nt++) {
                int n = warp_n * 32 + nt * 8 + gid;
                bP[nt][0] = Bw[0][s][tg][n];
                bP[nt][1] = Bw[0][s][4 + tg][n];
                bQ[nt][0] = Bw[1][s][tg][n];
                bQ[nt][1] = Bw[1][s][4 + tg][n];
            }
#pragma unroll
            for (int mt = 0; mt < 2; mt++) {
                int m = warp_m * 32 + mt * 16;
                __nv_bfloat162 hs0 = u2bf(Hsp[m + gid][s * 8 + tg]);
                __nv_bfloat162 hs1 = u2bf(Hsp[m + 8 + gid][s * 8 + tg]);
                __nv_bfloat162 hs2 = u2bf(Hsp[m + gid][s * 8 + 4 + tg]);
                __nv_bfloat162 hs3 = u2bf(Hsp[m + 8 + gid][s * 8 + 4 + tg]);
                __nv_bfloat162 hd0 = u2bf(Hdp[m + gid][s * 8 + tg]);
                __nv_bfloat162 hd1 = u2bf(Hdp[m + 8 + gid][s * 8 + tg]);
                __nv_bfloat162 hd2 = u2bf(Hdp[m + gid][s * 8 + 4 + tg]);
                __nv_bfloat162 hd3 = u2bf(Hdp[m + 8 + gid][s * 8 + 4 + tg]);
                unsigned p0 = bf2u(__hmul2(hs0, hd0));
                unsigned p1 = bf2u(__hmul2(hs1, hd1));
                unsigned p2 = bf2u(__hmul2(hs2, hd2));
                unsigned p3 = bf2u(__hmul2(hs3, hd3));
                unsigned q0 = bf2u(__habs2(__hsub2(hs0, hd0)));
                unsigned q1 = bf2u(__habs2(__hsub2(hs1, hd1)));
                unsigned q2 = bf2u(__habs2(__hsub2(hs2, hd2)));
                unsigned q3 = bf2u(__habs2(__hsub2(hs3, hd3)));
#pragma unroll
                for (int nt = 0; nt < 4; nt++) {
                    MMA_BF16(acc[mt][nt], p0, p1, p2, p3, bP[nt][0], bP[nt][1]);
                    MMA_BF16(acc[mt][nt], q0, q1, q2, q3, bQ[nt][0], bQ[nt][1]);
                }
            }
        }
        __syncthreads();
    }

    // ---- epilogue: struct feats + bias + relu + w2 dot, reduce into wsum ----
#pragma unroll
    for (int mt = 0; mt < 2; mt++) {
#pragma unroll
        for (int rh = 0; rh < 2; rh++) {
            int e = warp_m * 32 + mt * 16 + rh * 8 + gid;
            float s0 = s0s[e], s1 = s1s[e];
            float partial = 0.f;
#pragma unroll
            for (int nt = 0; nt < 4; nt++) {
#pragma unroll
                for (int cc = 0; cc < 2; cc++) {
                    int u = warp_n * 32 + nt * 8 + 2 * tg + cc;
                    float v = acc[mt][nt][rh * 2 + cc];
                    v += s0 * Wg0[u] + s1 * Wg1[u] + b1s[u];
                    v = fmaxf(v, 0.f);
                    partial += v * w2s[u];
                }
            }
            atomicAdd(&wsum[e], partial);
        }
    }
    __syncthreads();
    if (tid < 128) {
        float wr = wsum[tid] + B2[0];
        g_w[e0 + tid] = W_MAXC / (1.f + expf(-wr));
    }
}

// ------------------- fp16 row helpers ----------------------------------------
__device__ __forceinline__ void load8h(const __half2* p, float* r) {
    uint4 v = *(const uint4*)p;
    float2 f0 = __half22float2(*(__half2*)&v.x);
    float2 f1 = __half22float2(*(__half2*)&v.y);
    float2 f2 = __half22float2(*(__half2*)&v.z);
    float2 f3 = __half22float2(*(__half2*)&v.w);
    r[0]=f0.x; r[1]=f0.y; r[2]=f1.x; r[3]=f1.y;
    r[4]=f2.x; r[5]=f2.y; r[6]=f3.x; r[7]=f3.y;
}
__device__ __forceinline__ void store8h(__half2* p, const float* r) {
    uint4 v;
    __half2 h0 = __floats2half2_rn(r[0], r[1]);
    __half2 h1 = __floats2half2_rn(r[2], r[3]);
    __half2 h2 = __floats2half2_rn(r[4], r[5]);
    __half2 h3 = __floats2half2_rn(r[6], r[7]);
    v.x = *(unsigned*)&h0; v.y = *(unsigned*)&h1;
    v.z = *(unsigned*)&h2; v.w = *(unsigned*)&h3;
    *(uint4*)p = v;
}
__device__ __forceinline__ void load8(const float* p, float* r) {
    float4 v0 = *(const float4*)p;
    float4 v1 = *(const float4*)(p + 4);
    r[0]=v0.x; r[1]=v0.y; r[2]=v0.z; r[3]=v0.w;
    r[4]=v1.x; r[5]=v1.y; r[6]=v1.z; r[7]=v1.w;
}
__device__ __forceinline__ void store8(float* p, const float* r) {
    *(float4*)p       = make_float4(r[0], r[1], r[2], r[3]);
    *(float4*)(p + 4) = make_float4(r[4], r[5], r[6], r[7]);
}

// ------------------- init m = softmax(log_phi[src]) over all E edges ----------
__global__ void init_m_k(const int* __restrict__ srcAll) {
    int e = blockIdx.x * blockDim.x + threadIdx.x;
    if (e >= EEC) return;
    int s = srcAll[e];
    float lp[8];
    load8(g_logphi + s * 8, lp);
    float mx = -1e30f;
#pragma unroll
    for (int c = 0; c < 8; c++) mx = fmaxf(mx, lp[c]);
    float ex[8], sm = 0.f;
#pragma unroll
    for (int c = 0; c < 8; c++) { ex[c] = expf(lp[c] - mx); sm += ex[c]; }
    float inv = 1.f / sm;
    float o[8];
#pragma unroll
    for (int c = 0; c < 8; c++) o[c] = ex[c] * inv;
    store8h(g_m + (size_t)e * 4, o);
}

// ------------------- node kernel: b16 = lp + alpha*sum_cur; zero sum_nxt ------
__global__ void node_k(const float* __restrict__ sum_cur,
                       float* __restrict__ sum_nxt) {
    int n = blockIdx.x * blockDim.x + threadIdx.x;
    if (n >= NN) return;
    float alpha = g_alpha;
    float lp[8], si[8], b[8];
    load8(g_logphi + n * 8, lp);
    load8(sum_cur + n * 8, si);
#pragma unroll
    for (int c = 0; c < 8; c++) b[c] = lp[c] + alpha * si[c];
    store8h(g_b16 + n * 4, b);
    float4 z = make_float4(0.f, 0.f, 0.f, 0.f);
    *(float4*)(sum_nxt + n * 8)     = z;
    *(float4*)(sum_nxt + n * 8 + 4) = z;
}

// ------------------- BP core helpers -----------------------------------------
__device__ __forceinline__ void upd_m(float* mrow, const float* b,
                                      const float* lf_rev, float alpha) {
    float t[8], mx = -1e30f;
#pragma unroll
    for (int c = 0; c < 8; c++) { t[c] = b[c] - alpha * lf_rev[c]; mx = fmaxf(mx, t[c]); }
    float ex[8], sm = 0.f;
#pragma unroll
    for (int c = 0; c < 8; c++) { ex[c] = __expf(t[c] - mx); sm += ex[c]; }
    float inv = 1.f / sm;
    float m[8], tot = 0.f;
#pragma unroll
    for (int c = 0; c < 8; c++) {
        m[c] = (1.f - ETA_C) * mrow[c] + ETA_C * (ex[c] * inv);
        m[c] = fmaxf(m[c], EPS_C);
        tot += m[c];
    }
    float it = 1.f / tot;
#pragma unroll
    for (int c = 0; c < 8; c++) mrow[c] = m[c] * it;
}
// K = exp(w*R) is symmetric (R symmetric): 36 distinct exps, shared by both
// directions. f1 = m1 K, f2 = m2 K, then lf = log(max(f, eps)) * en.
__device__ __forceinline__ void msg_lf2(const float* Rs, float w,
                                        const float* m1, const float* m2,
                                        float en, float* lf1, float* lf2) {
    float f1[8], f2[8];
#pragma unroll
    for (int c = 0; c < 8; c++) {
        float k = __expf(w * Rs[c * 9]);        // diagonal
        f1[c] = m1[c] * k;
        f2[c] = m2[c] * k;
    }
#pragma unroll
    for (int c = 0; c < 8; c++) {
#pragma unroll
        for (int d = c + 1; d < 8; d++) {
            float k = __expf(w * Rs[c * 8 + d]);
            f1[d] += m1[c] * k;  f1[c] += m1[d] * k;
            f2[d] += m2[c] * k;  f2[c] += m2[d] * k;
        }
    }
#pragma unroll
    for (int c = 0; c < 8; c++) {
        lf1[c] = __logf(fmaxf(f1[c], EPS_C)) * en;
        lf2[c] = __logf(fmaxf(f2[c], EPS_C)) * en;
    }
}

// ------------------- first half-iteration: sum from current m (no lf store) ---
__global__ __launch_bounds__(256) void iterA_k(const int* __restrict__ src,
                                               const int* __restrict__ dst,
                                               float* __restrict__ sum_w) {
    __shared__ float Rs[64];
    if (threadIdx.x < 64) Rs[threadIdx.x] = g_Rs[threadIdx.x];
    __syncthreads();
    int e = blockIdx.x * blockDim.x + threadIdx.x;
    if (e >= E2C) return;
    float w = g_w[e], en = g_en[e];
    int s = src[e], d = dst[e];
    float m1[8], m2[8], lf1[8], lf2[8];
    load8h(g_m + (size_t)e * 4, m1);
    load8h(g_m + (size_t)(e + E2C) * 4, m2);
    msg_lf2(Rs, w, m1, m2, en, lf1, lf2);
    red4(sum_w + d * 8,     lf1[0], lf1[1], lf1[2], lf1[3]);
    red4(sum_w + d * 8 + 4, lf1[4], lf1[5], lf1[6], lf1[7]);
    red4(sum_w + s * 8,     lf2[0], lf2[1], lf2[2], lf2[3]);
    red4(sum_w + s * 8 + 4, lf2[4], lf2[5], lf2[6], lf2[7]);
}

// ------------------- fused BP iteration (recompute old lf from m) -------------
__global__ __launch_bounds__(256) void fused_k(const int* __restrict__ src,
                                               const int* __restrict__ dst,
                                               float* __restrict__ sum_w) {
    __shared__ float Rs[64];
    if (threadIdx.x < 64) Rs[threadIdx.x] = g_Rs[threadIdx.x];
    __syncthreads();
    int e = blockIdx.x * blockDim.x + threadIdx.x;
    if (e >= E2C) return;
    float alpha = g_alpha;
    int s = src[e], d = dst[e];
    float m1[8], m2[8], lf1[8], lf2[8];
    load8h(g_m + (size_t)e * 4, m1);
    load8h(g_m + (size_t)(e + E2C) * 4, m2);
    float w = g_w[e], en = g_en[e];
    // old lf recomputed from old m (pure function; replaces the g_lf array)
    msg_lf2(Rs, w, m1, m2, en, lf1, lf2);
    {
        float bs[8];
        load8h(g_b16 + s * 4, bs);
        upd_m(m1, bs, lf2, alpha);   // dir s->d: t = b[s] - alpha*lf(rev)
    }
    {
        float bd[8];
        load8h(g_b16 + d * 4, bd);
        upd_m(m2, bd, lf1, alpha);   // dir d->s: t = b[d] - alpha*lf1
    }
    store8h(g_m + (size_t)e * 4, m1);
    store8h(g_m + (size_t)(e + E2C) * 4, m2);
    float nlf1[8], nlf2[8];
    msg_lf2(Rs, w, m1, m2, en, nlf1, nlf2);
    red4(sum_w + d * 8,     nlf1[0], nlf1[1], nlf1[2], nlf1[3]);
    red4(sum_w + d * 8 + 4, nlf1[4], nlf1[5], nlf1[6], nlf1[7]);
    red4(sum_w + s * 8,     nlf2[0], nlf2[1], nlf2[2], nlf2[3]);
    red4(sum_w + s * 8 + 4, nlf2[4], nlf2[5], nlf2[6], nlf2[7]);
}

// ------------------- final beliefs -------------------------------------------
__global__ void beliefs_k(const float* __restrict__ sum_r, float* __restrict__ out) {
    int n = blockIdx.x * blockDim.x + threadIdx.x;
    if (n >= NN) return;
    float alpha = g_alpha;
    float lp[8], si[8];
    load8(g_logphi + n * 8, lp);
    load8(sum_r + n * 8, si);
    float t[8], mx = -1e30f;
#pragma unroll
    for (int c = 0; c < 8; c++) { t[c] = lp[c] + alpha * si[c]; mx = fmaxf(mx, t[c]); }
    float ex[8], sm = 0.f;
#pragma unroll
    for (int c = 0; c < 8; c++) { ex[c] = expf(t[c] - mx); sm += ex[c]; }
    float inv = 1.f / sm;
    float o[8];
#pragma unroll
    for (int c = 0; c < 8; c++) o[c] = ex[c] * inv;
    store8(out + (size_t)n * 8, o);
}

// ------------------- launcher -------------------------------------------------
extern "C" void kernel_launch(void* const* d_in, const int* in_sizes, int n_in,
                              void* d_out, int out_size) {
    const float* x      = (const float*)d_in[0];
    const int*   ei     = (const int*)  d_in[1];   // [2, E] : row0 src, row1 dst
    const float* enc_w1 = (const float*)d_in[3];
    const float* enc_b1 = (const float*)d_in[4];
    const float* enc_w2 = (const float*)d_in[5];
    const float* enc_b2 = (const float*)d_in[6];
    const float* edge_w1= (const float*)d_in[7];
    const float* edge_b1= (const float*)d_in[8];
    const float* edge_w2= (const float*)d_in[9];
    const float* edge_b2= (const float*)d_in[10];
    const float* R_raw  = (const float*)d_in[11];
    const float* rsl    = (const float*)d_in[12];
    const float* msg    = (const float*)d_in[13];
    float* out = (float*)d_out;

    const int* src = ei;         // first E2 entries of row0 are unique-edge srcs
    const int* dst = ei + EEC;   // row1

    float* sumA; cudaGetSymbolAddress((void**)&sumA, g_sumA);
    float* sumB; cudaGetSymbolAddress((void**)&sumB, g_sumB);

    prep0_k<<<(NN + 255) / 256, 256>>>(R_raw, rsl, msg);
    enc_gemm_k<<<dim3((NN + 127) / 128, HID / 64), 256>>>(x, enc_w1, enc_b1);
    deg_k<<<(E2C + 255) / 256, 256>>>(src, dst);
    edge_mlp_k<<<E2C / 128, 256>>>(src, dst, edge_w1, edge_b1, edge_w2, edge_b2);
    logits_k<<<(NN * 32 + 255) / 256, 256>>>(enc_w2, enc_b2);
    init_m_k<<<(EEC + 255) / 256, 256>>>(src);  // row0 spans all E directed edges

    const int NC4 = NN * CC / 4;
    zero4_k<<<(NC4 + 255) / 256, 256>>>((float4*)sumA, NC4);
    iterA_k<<<(E2C + 255) / 256, 256>>>(src, dst, sumA);

    float* cur = sumA;
    float* nxt = sumB;
    for (int t = 0; t < T_ITERS; t++) {
        node_k<<<(NN + 255) / 256, 256>>>(cur, nxt);   // b16 = lp + a*cur ; nxt = 0
        fused_k<<<(E2C + 255) / 256, 256>>>(src, dst, nxt);
        float* tmp = cur; cur = nxt; nxt = tmp;
    }
    beliefs_k<<<(NN + 255) / 256, 256>>>(cur, out);
}

// round 15
// speedup vs baseline: 1.0798x; 1.0798x over previous
#include <cuda_runtime.h>
#include <cuda_fp16.h>
#include <cuda_bf16.h>
#include <math.h>

#define NN      50000
#define INDIM   512
#define HID     256
#define CC      8
#define E2C     400000
#define EEC     800000
#define T_ITERS 10
#define ETA_C   0.2f
#define W_MAXC  0.8f
#define ALPHA_MAXC 1.5f
#define EPS_C   1e-12f

// ------------------- scratch (device globals; no allocation allowed) ---------
__device__ __align__(16) float g_h[NN * HID];            // 51.2 MB (fp32, logits)
__device__ __align__(16) __nv_bfloat162 g_hb[NN * HID / 2]; // 25.6 MB (bf16, edge MLP)
__device__ __align__(16) float g_logphi[NN * CC];
__device__ __align__(16) float g_deg[NN];
__device__ __align__(16) float g_w[E2C];
__device__ __align__(16) float g_en[E2C];
__device__ __align__(16) __half2 g_m[EEC * 4];       // 12.8 MB (fp16)
__device__ __align__(16) __half2 g_lf[EEC * 4];      // 12.8 MB (fp16)
__device__ __align__(16) __half2 g_sum16A[NN * 4];   // fp16 sums
__device__ __align__(16) __half2 g_sum16B[NN * 4];
__device__ __align__(16) __half2 g_b16[NN * 4];      // fp16 b = lp + alpha*sum
__device__ __align__(16) float g_Rs[64];
__device__ float g_alpha;

// ------------------- bf16 pack helpers ----------------------------------------
__device__ __forceinline__ unsigned pack_bf16(__nv_bfloat16 lo, __nv_bfloat16 hi) {
    return ((unsigned)__bfloat16_as_ushort(hi) << 16) | __bfloat16_as_ushort(lo);
}
__device__ __forceinline__ unsigned pack_bf16f(float lo, float hi) {
    __nv_bfloat162 t = __floats2bfloat162_rn(lo, hi);
    return *(unsigned*)&t;
}
__device__ __forceinline__ __nv_bfloat162 u2bf(unsigned x) {
    __nv_bfloat162 r; *(unsigned*)&r = x; return r;
}
__device__ __forceinline__ unsigned bf2u(__nv_bfloat162 x) {
    return *(unsigned*)&x;
}

#define MMA_BF16(accp, a0, a1, a2, a3, b0, b1) \
    asm("mma.sync.aligned.m16n8k16.row.col.f32.bf16.bf16.f32 " \
        "{%0,%1,%2,%3}, {%4,%5,%6,%7}, {%8,%9}, {%0,%1,%2,%3};" \
        : "+f"((accp)[0]), "+f"((accp)[1]), "+f"((accp)[2]), "+f"((accp)[3]) \
        : "r"(a0), "r"(a1), "r"(a2), "r"(a3), "r"(b0), "r"(b1))

// ------------------- fp16 vector reduction (atomic add, no return) ------------
__device__ __forceinline__ void red8h(__half2* p, const float* v) {
    __half2 h0 = __floats2half2_rn(v[0], v[1]);
    __half2 h1 = __floats2half2_rn(v[2], v[3]);
    __half2 h2 = __floats2half2_rn(v[4], v[5]);
    __half2 h3 = __floats2half2_rn(v[6], v[7]);
    asm volatile("red.global.add.noftz.v4.f16x2 [%0], {%1, %2, %3, %4};"
                 :: "l"(p), "r"(*(unsigned*)&h0), "r"(*(unsigned*)&h1),
                    "r"(*(unsigned*)&h2), "r"(*(unsigned*)&h3) : "memory");
}

// ------------------- generic zero --------------------------------------------
__global__ void zero4_k(float4* __restrict__ p, int n4) {
    int i = blockIdx.x * blockDim.x + threadIdx.x;
    if (i < n4) p[i] = make_float4(0.f, 0.f, 0.f, 0.f);
}

// ------------------- prep: zero deg + symmetrized R + alpha -------------------
__global__ void prep0_k(const float* __restrict__ R_raw,
                        const float* __restrict__ rsl,
                        const float* __restrict__ msg) {
    int i = blockIdx.x * blockDim.x + threadIdx.x;
    if (i < NN) g_deg[i] = 0.f;
    if (blockIdx.x == 0) {
        int t = threadIdx.x;
        if (t == 0) g_alpha = ALPHA_MAXC / (1.f + expf(-msg[0]));
        if (t < 64) {
            int c = t >> 3, d = t & 7;
            float r = 0.5f * (R_raw[c * 8 + d] + R_raw[d * 8 + c]);
            float xr = rsl[0];
            float sp = (xr > 20.f) ? xr : log1pf(expf(xr));
            g_Rs[t] = (sp + 1e-6f) * tanhf(r);
        }
    }
}

// ------------------- encoder GEMM via split-bf16 mma.sync ---------------------
__global__ __launch_bounds__(256, 3) void enc_gemm_k(const float* __restrict__ X,
                                                     const float* __restrict__ W,
                                                     const float* __restrict__ B) {
    __shared__ unsigned Ahi[128][20], Alo[128][20];   // bf16x2 pairs (16/row) pad 20
    __shared__ unsigned Bpk[2][2][8][68];             // [mat][s][rp][n] pad 68

    int tid  = threadIdx.x;
    int wid  = tid >> 5;
    int lane = tid & 31;
    int gid  = lane >> 2;
    int tg   = lane & 3;
    int warp_m = wid & 3;          // 4 x 32 rows
    int warp_n = wid >> 2;         // 2 x 32 cols
    int row0 = blockIdx.x * 128;
    int col0 = blockIdx.y * 64;

    float acc[2][4][4];
#pragma unroll
    for (int mt = 0; mt < 2; mt++)
#pragma unroll
        for (int nt = 0; nt < 4; nt++)
#pragma unroll
            for (int r = 0; r < 4; r++) acc[mt][nt][r] = 0.f;

    for (int f0 = 0; f0 < INDIM; f0 += 32) {
        // ---- stage A: 128 rows x 32 k, hi/lo split, pair-packed ----
#pragma unroll
        for (int i = 0; i < 4; i++) {
            int idx = tid + i * 256;
            int row = idx >> 3;
            int f4  = idx & 7;
            int gr = row0 + row;
            float4 v = make_float4(0.f, 0.f, 0.f, 0.f);
            if (gr < NN) v = *(const float4*)(X + (size_t)gr * INDIM + f0 + f4 * 4);
            __nv_bfloat16 hx = __float2bfloat16(v.x);
            __nv_bfloat16 hy = __float2bfloat16(v.y);
            __nv_bfloat16 hz = __float2bfloat16(v.z);
            __nv_bfloat16 hw = __float2bfloat16(v.w);
            Ahi[row][f4 * 2]     = pack_bf16(hx, hy);
            Ahi[row][f4 * 2 + 1] = pack_bf16(hz, hw);
            Alo[row][f4 * 2]     = pack_bf16f(v.x - __bfloat162float(hx),
                                              v.y - __bfloat162float(hy));
            Alo[row][f4 * 2 + 1] = pack_bf16f(v.z - __bfloat162float(hz),
                                              v.w - __bfloat162float(hw));
        }
        // ---- stage B: 32 k rows x 64 cols of W, hi/lo, pair-packed ----
        {
            int s  = tid >> 7;             // 0..1 (k16 step)
            int rp = (tid >> 4) & 7;       // 0..7 = 2*tg + half
            int n0 = (tid & 15) * 4;
            int k0 = f0 + s * 16 + (rp & 1) * 8 + (rp >> 1) * 2;
            float4 w0 = *(const float4*)(W + (size_t)k0 * HID + col0 + n0);
            float4 w1 = *(const float4*)(W + (size_t)(k0 + 1) * HID + col0 + n0);
            __nv_bfloat16 h00 = __float2bfloat16(w0.x), h10 = __float2bfloat16(w1.x);
            __nv_bfloat16 h01 = __float2bfloat16(w0.y), h11 = __float2bfloat16(w1.y);
            __nv_bfloat16 h02 = __float2bfloat16(w0.z), h12 = __float2bfloat16(w1.z);
            __nv_bfloat16 h03 = __float2bfloat16(w0.w), h13 = __float2bfloat16(w1.w);
            Bpk[0][s][rp][n0 + 0] = pack_bf16(h00, h10);
            Bpk[0][s][rp][n0 + 1] = pack_bf16(h01, h11);
            Bpk[0][s][rp][n0 + 2] = pack_bf16(h02, h12);
            Bpk[0][s][rp][n0 + 3] = pack_bf16(h03, h13);
            Bpk[1][s][rp][n0 + 0] = pack_bf16f(w0.x - __bfloat162float(h00),
                                               w1.x - __bfloat162float(h10));
            Bpk[1][s][rp][n0 + 1] = pack_bf16f(w0.y - __bfloat162float(h01),
                                               w1.y - __bfloat162float(h11));
            Bpk[1][s][rp][n0 + 2] = pack_bf16f(w0.z - __bfloat162float(h02),
                                               w1.z - __bfloat162float(h12));
            Bpk[1][s][rp][n0 + 3] = pack_bf16f(w0.w - __bfloat162float(h03),
                                               w1.w - __bfloat162float(h13));
        }
        __syncthreads();

        // ---- compute: 2 k16 steps ----
#pragma unroll
        for (int s = 0; s < 2; s++) {
            unsigned bh[4][2], bl[4][2];
#pragma unroll
            for (int nt = 0; nt < 4; nt++) {
                int n = warp_n * 32 + nt * 8 + gid;
                bh[nt][0] = Bpk[0][s][2 * tg][n];
                bh[nt][1] = Bpk[0][s][2 * tg + 1][n];
                bl[nt][0] = Bpk[1][s][2 * tg][n];
                bl[nt][1] = Bpk[1][s][2 * tg + 1][n];
            }
#pragma unroll
            for (int mt = 0; mt < 2; mt++) {
                int m = warp_m * 32 + mt * 16;
                unsigned ah0 = Ahi[m + gid][s * 8 + tg];
                unsigned ah1 = Ahi[m + 8 + gid][s * 8 + tg];
                unsigned ah2 = Ahi[m + gid][s * 8 + 4 + tg];
                unsigned ah3 = Ahi[m + 8 + gid][s * 8 + 4 + tg];
                unsigned al0 = Alo[m + gid][s * 8 + tg];
                unsigned al1 = Alo[m + 8 + gid][s * 8 + tg];
                unsigned al2 = Alo[m + gid][s * 8 + 4 + tg];
                unsigned al3 = Alo[m + 8 + gid][s * 8 + 4 + tg];
#pragma unroll
                for (int nt = 0; nt < 4; nt++) {
                    MMA_BF16(acc[mt][nt], ah0, ah1, ah2, ah3, bh[nt][0], bh[nt][1]);
                    MMA_BF16(acc[mt][nt], ah0, ah1, ah2, ah3, bl[nt][0], bl[nt][1]);
                    MMA_BF16(acc[mt][nt], al0, al1, al2, al3, bh[nt][0], bh[nt][1]);
                }
            }
        }
        __syncthreads();
    }

    // ---- epilogue: bias + relu, fp32 + bf16 stores ----
#pragma unroll
    for (int mt = 0; mt < 2; mt++) {
#pragma unroll
        for (int nt = 0; nt < 4; nt++) {
            int col = col0 + warp_n * 32 + nt * 8 + 2 * tg;
            float2 bv = *(const float2*)(B + col);
            int r0 = row0 + warp_m * 32 + mt * 16 + gid;
            if (r0 < NN) {
                float2 o;
                o.x = fmaxf(acc[mt][nt][0] + bv.x, 0.f);
                o.y = fmaxf(acc[mt][nt][1] + bv.y, 0.f);
                *(float2*)(g_h + (size_t)r0 * HID + col) = o;
                g_hb[((size_t)r0 * HID + col) >> 1] = __floats2bfloat162_rn(o.x, o.y);
            }
            int r1 = r0 + 8;
            if (r1 < NN) {
                float2 o;
                o.x = fmaxf(acc[mt][nt][2] + bv.x, 0.f);
                o.y = fmaxf(acc[mt][nt][3] + bv.y, 0.f);
                *(float2*)(g_h + (size_t)r1 * HID + col) = o;
                g_hb[((size_t)r1 * HID + col) >> 1] = __floats2bfloat162_rn(o.x, o.y);
            }
        }
    }
}

// ------------------- logits + log_softmax: one warp per node ------------------
__global__ void logits_k(const float* __restrict__ W2, const float* __restrict__ B2) {
    int gt = blockIdx.x * blockDim.x + threadIdx.x;
    int node = gt >> 5, lane = gt & 31;
    if (node >= NN) return;
    const float* hrow = g_h + (size_t)node * HID;
    float acc[8];
#pragma unroll
    for (int c = 0; c < 8; c++) acc[c] = 0.f;
    for (int j = lane; j < HID; j += 32) {
        float hv = hrow[j];
        float4 wA = *(const float4*)(W2 + j * 8);
        float4 wB = *(const float4*)(W2 + j * 8 + 4);
        acc[0] += hv * wA.x; acc[1] += hv * wA.y;
        acc[2] += hv * wA.z; acc[3] += hv * wA.w;
        acc[4] += hv * wB.x; acc[5] += hv * wB.y;
        acc[6] += hv * wB.z; acc[7] += hv * wB.w;
    }
#pragma unroll
    for (int c = 0; c < 8; c++)
#pragma unroll
        for (int off = 16; off; off >>= 1)
            acc[c] += __shfl_xor_sync(0xffffffffu, acc[c], off);
    if (lane == 0) {
        float lg[8], mx = -1e30f;
#pragma unroll
        for (int c = 0; c < 8; c++) { lg[c] = acc[c] + B2[c]; mx = fmaxf(mx, lg[c]); }
        float s = 0.f;
#pragma unroll
        for (int c = 0; c < 8; c++) s += expf(lg[c] - mx);
        float lse = mx + logf(s);
        *(float4*)(g_logphi + node * 8)     = make_float4(lg[0]-lse, lg[1]-lse, lg[2]-lse, lg[3]-lse);
        *(float4*)(g_logphi + node * 8 + 4) = make_float4(lg[4]-lse, lg[5]-lse, lg[6]-lse, lg[7]-lse);
    }
}

// ------------------- degrees -------------------------------------------------
__global__ void deg_k(const int* __restrict__ src, const int* __restrict__ dst) {
    int e = blockIdx.x * blockDim.x + threadIdx.x;
    if (e >= E2C) return;
    atomicAdd(&g_deg[src[e]], 1.f);
    atomicAdd(&g_deg[dst[e]], 1.f);
}

// ------------------- edge MLP via bf16 mma.sync (m16n8k16) --------------------
__global__ __launch_bounds__(256, 3) void edge_mlp_k(const int* __restrict__ src,
                                                     const int* __restrict__ dst,
                                                     const float* __restrict__ W1,
                                                     const float* __restrict__ B1,
                                                     const float* __restrict__ W2,
                                                     const float* __restrict__ B2) {
    __shared__ int   ss[128], dd[128];
    __shared__ float s0s[128], s1s[128];
    __shared__ unsigned Hsp[128][20], Hdp[128][20];  // bf16x2 pairs, 16/row, pad 20
    __shared__ unsigned Bw[2][2][8][72];             // [part][s][rp][n] bf16x2 pairs
    __shared__ float Wg0[64], Wg1[64], b1s[64], w2s[64];
    __shared__ float wsum[128];

    int tid  = threadIdx.x;
    int wid  = tid >> 5;
    int lane = tid & 31;
    int gid  = lane >> 2;      // group id 0..7
    int tg   = lane & 3;       // thread-in-group 0..3
    int warp_m = wid & 3;      // 4 m-warps * 32 edges
    int warp_n = wid >> 2;     // 2 n-warps * 32 cols
    int e0 = blockIdx.x * 128;

    if (tid < 128) {
        int ge = e0 + tid;
        int s = src[ge], d = dst[ge];
        ss[tid] = s; dd[tid] = d;
        float degs = g_deg[s], degd = g_deg[d];
        float a = logf(degs + 1.f), b = logf(degd + 1.f);
        s0s[tid] = a + b; s1s[tid] = fabsf(a - b);
        float ds = fmaxf(degs, 1.f), dd2 = fmaxf(degd, 1.f);
        g_en[ge] = rsqrtf(ds * dd2);
        wsum[tid] = 0.f;
    } else {
        int t = tid - 128;
        if (t < 64) { Wg0[t] = W1[512 * 64 + t]; b1s[t] = B1[t]; }
        else { int u = t - 64; Wg1[u] = W1[513 * 64 + u]; w2s[u] = W2[u]; }
    }
    __syncthreads();

    float acc[2][4][4];
#pragma unroll
    for (int mt = 0; mt < 2; mt++)
#pragma unroll
        for (int nt = 0; nt < 4; nt++)
#pragma unroll
            for (int r = 0; r < 4; r++) acc[mt][nt][r] = 0.f;

    for (int f0 = 0; f0 < HID; f0 += 32) {
        // ---- stage A: raw bf16x2 copies of hs/hd rows (no conversion) ----
        {
            int e = tid >> 1;
            int half = tid & 1;
            const uint4* hs4 = (const uint4*)(g_hb + (((size_t)ss[e] * HID + f0) >> 1) + half * 8);
            const uint4* hd4 = (const uint4*)(g_hb + (((size_t)dd[e] * HID + f0) >> 1) + half * 8);
#pragma unroll
            for (int j = 0; j < 2; j++) {
                *(uint4*)&Hsp[e][half * 8 + j * 4] = hs4[j];
                *(uint4*)&Hdp[e][half * 8 + j * 4] = hd4[j];
            }
        }
        // ---- stage B: weight k-pairs as bf16x2, both parts ----
        {
            int part = tid >> 7;           // 0..1
            int s    = (tid >> 6) & 1;     // 0..1
            int rp   = (tid >> 3) & 7;     // 0..7: (rp>>2)=khalf, (rp&3)=tg
            int n0   = (tid & 7) * 8;
            int rk = (part ? 256 : 0) + f0 + s * 16 + (rp >> 2) * 8 + (rp & 3) * 2;
            const float* Wp = W1 + (size_t)rk * 64 + n0;
            float4 w0a = *(const float4*)(Wp);
            float4 w0b = *(const float4*)(Wp + 4);
            float4 w1a = *(const float4*)(Wp + 64);
            float4 w1b = *(const float4*)(Wp + 68);
            unsigned* o = &Bw[part][s][rp][n0];
            o[0] = pack_bf16f(w0a.x, w1a.x);
            o[1] = pack_bf16f(w0a.y, w1a.y);
            o[2] = pack_bf16f(w0a.z, w1a.z);
            o[3] = pack_bf16f(w0a.w, w1a.w);
            o[4] = pack_bf16f(w0b.x, w1b.x);
            o[5] = pack_bf16f(w0b.y, w1b.y);
            o[6] = pack_bf16f(w0b.z, w1b.z);
            o[7] = pack_bf16f(w0b.w, w1b.w);
        }
        __syncthreads();

        // ---- compute: 2 k16 steps; P/Q built from one hs/hd load set ----
#pragma unroll
        for (int s = 0; s < 2; s++) {
            unsigned bP[4][2], bQ[4][2];
#pragma unroll
            for (int nt = 0; nt < 4; nt++) {
                int n = warp_n * 32 + nt * 8 + gid;
                bP[nt][0] = Bw[0][s][tg][n];
                bP[nt][1] = Bw[0][s][4 + tg][n];
                bQ[nt][0] = Bw[1][s][tg][n];
                bQ[nt][1] = Bw[1][s][4 + tg][n];
            }
#pragma unroll
            for (int mt = 0; mt < 2; mt++) {
                int m = warp_m * 32 + mt * 16;
                __nv_bfloat162 hs0 = u2bf(Hsp[m + gid][s * 8 + tg]);
                __nv_bfloat162 hs1 = u2bf(Hsp[m + 8 + gid][s * 8 + tg]);
                __nv_bfloat162 hs2 = u2bf(Hsp[m + gid][s * 8 + 4 + tg]);
                __nv_bfloat162 hs3 = u2bf(Hsp[m + 8 + gid][s * 8 + 4 + tg]);
                __nv_bfloat162 hd0 = u2bf(Hdp[m + gid][s * 8 + tg]);
                __nv_bfloat162 hd1 = u2bf(Hdp[m + 8 + gid][s * 8 + tg]);
                __nv_bfloat162 hd2 = u2bf(Hdp[m + gid][s * 8 + 4 + tg]);
                __nv_bfloat162 hd3 = u2bf(Hdp[m + 8 + gid][s * 8 + 4 + tg]);
                unsigned p0 = bf2u(__hmul2(hs0, hd0));
                unsigned p1 = bf2u(__hmul2(hs1, hd1));
                unsigned p2 = bf2u(__hmul2(hs2, hd2));
                unsigned p3 = bf2u(__hmul2(hs3, hd3));
                unsigned q0 = bf2u(__habs2(__hsub2(hs0, hd0)));
                unsigned q1 = bf2u(__habs2(__hsub2(hs1, hd1)));
                unsigned q2 = bf2u(__habs2(__hsub2(hs2, hd2)));
                unsigned q3 = bf2u(__habs2(__hsub2(hs3, hd3)));
#pragma unroll
                for (int nt = 0; nt < 4; nt++) {
                    MMA_BF16(acc[mt][nt], p0, p1, p2, p3, bP[nt][0], bP[nt][1]);
                    MMA_BF16(acc[mt][nt], q0, q1, q2, q3, bQ[nt][0], bQ[nt][1]);
                }
            }
        }
        __syncthreads();
    }

    // ---- epilogue: struct feats + bias + relu + w2 dot, reduce into wsum ----
#pragma unroll
    for (int mt = 0; mt < 2; mt++) {
#pragma unroll
        for (int rh = 0; rh < 2; rh++) {
            int e = warp_m * 32 + mt * 16 + rh * 8 + gid;
            float s0 = s0s[e], s1 = s1s[e];
            float partial = 0.f;
#pragma unroll
            for (int nt = 0; nt < 4; nt++) {
#pragma unroll
                for (int cc = 0; cc < 2; cc++) {
                    int u = warp_n * 32 + nt * 8 + 2 * tg + cc;
                    float v = acc[mt][nt][rh * 2 + cc];
                    v += s0 * Wg0[u] + s1 * Wg1[u] + b1s[u];
                    v = fmaxf(v, 0.f);
                    partial += v * w2s[u];
                }
            }
            atomicAdd(&wsum[e], partial);
        }
    }
    __syncthreads();
    if (tid < 128) {
        float wr = wsum[tid] + B2[0];
        g_w[e0 + tid] = W_MAXC / (1.f + expf(-wr));
    }
}

// ------------------- fp16 row helpers ----------------------------------------
__device__ __forceinline__ void load8h(const __half2* p, float* r) {
    uint4 v = *(const uint4*)p;
    float2 f0 = __half22float2(*(__half2*)&v.x);
    float2 f1 = __half22float2(*(__half2*)&v.y);
    float2 f2 = __half22float2(*(__half2*)&v.z);
    float2 f3 = __half22float2(*(__half2*)&v.w);
    r[0]=f0.x; r[1]=f0.y; r[2]=f1.x; r[3]=f1.y;
    r[4]=f2.x; r[5]=f2.y; r[6]=f3.x; r[7]=f3.y;
}
__device__ __forceinline__ void store8h(__half2* p, const float* r) {
    uint4 v;
    __half2 h0 = __floats2half2_rn(r[0], r[1]);
    __half2 h1 = __floats2half2_rn(r[2], r[3]);
    __half2 h2 = __floats2half2_rn(r[4], r[5]);
    __half2 h3 = __floats2half2_rn(r[6], r[7]);
    v.x = *(unsigned*)&h0; v.y = *(unsigned*)&h1;
    v.z = *(unsigned*)&h2; v.w = *(unsigned*)&h3;
    *(uint4*)p = v;
}
__device__ __forceinline__ void load8(const float* p, float* r) {
    float4 v0 = *(const float4*)p;
    float4 v1 = *(const float4*)(p + 4);
    r[0]=v0.x; r[1]=v0.y; r[2]=v0.z; r[3]=v0.w;
    r[4]=v1.x; r[5]=v1.y; r[6]=v1.z; r[7]=v1.w;
}
__device__ __forceinline__ void store8(float* p, const float* r) {
    *(float4*)p       = make_float4(r[0], r[1], r[2], r[3]);
    *(float4*)(p + 4) = make_float4(r[4], r[5], r[6], r[7]);
}

// ------------------- init m = softmax(log_phi[src]) over all E edges ----------
__global__ void init_m_k(const int* __restrict__ srcAll) {
    int e = blockIdx.x * blockDim.x + threadIdx.x;
    if (e >= EEC) return;
    int s = srcAll[e];
    float lp[8];
    load8(g_logphi + s * 8, lp);
    float mx = -1e30f;
#pragma unroll
    for (int c = 0; c < 8; c++) mx = fmaxf(mx, lp[c]);
    float ex[8], sm = 0.f;
#pragma unroll
    for (int c = 0; c < 8; c++) { ex[c] = expf(lp[c] - mx); sm += ex[c]; }
    float inv = 1.f / sm;
    float o[8];
#pragma unroll
    for (int c = 0; c < 8; c++) o[c] = ex[c] * inv;
    store8h(g_m + (size_t)e * 4, o);
}

// ------------------- node kernel: b16 = lp + alpha*sum_cur; zero sum_nxt ------
__global__ void node_k(const __half2* __restrict__ sum_cur,
                       __half2* __restrict__ sum_nxt) {
    int n = blockIdx.x * blockDim.x + threadIdx.x;
    if (n >= NN) return;
    float alpha = g_alpha;
    float lp[8], si[8], b[8];
    load8(g_logphi + n * 8, lp);
    load8h(sum_cur + n * 4, si);
#pragma unroll
    for (int c = 0; c < 8; c++) b[c] = lp[c] + alpha * si[c];
    store8h(g_b16 + n * 4, b);
    uint4 z = make_uint4(0u, 0u, 0u, 0u);
    *(uint4*)(sum_nxt + n * 4) = z;
}

// ------------------- BP core helpers -----------------------------------------
__device__ __forceinline__ void upd_m(float* mrow, const float* b,
                                      const float* lf_rev, float alpha) {
    float t[8], mx = -1e30f;
#pragma unroll
    for (int c = 0; c < 8; c++) { t[c] = b[c] - alpha * lf_rev[c]; mx = fmaxf(mx, t[c]); }
    float ex[8], sm = 0.f;
#pragma unroll
    for (int c = 0; c < 8; c++) { ex[c] = __expf(t[c] - mx); sm += ex[c]; }
    float inv = 1.f / sm;
    float m[8], tot = 0.f;
#pragma unroll
    for (int c = 0; c < 8; c++) {
        m[c] = (1.f - ETA_C) * mrow[c] + ETA_C * (ex[c] * inv);
        m[c] = fmaxf(m[c], EPS_C);
        tot += m[c];
    }
    float it = 1.f / tot;
#pragma unroll
    for (int c = 0; c < 8; c++) mrow[c] = m[c] * it;
}
// K = exp(w*R) is symmetric (R symmetric): 36 distinct exps, shared by both
// directions. f1 = m1 K, f2 = m2 K, then lf = log(max(f, eps)) * en.
__device__ __forceinline__ void msg_lf2(const float* Rs, float w,
                                        const float* m1, const float* m2,
                                        float en, float* lf1, float* lf2) {
    float f1[8], f2[8];
#pragma unroll
    for (int c = 0; c < 8; c++) {
        float k = __expf(w * Rs[c * 9]);        // diagonal
        f1[c] = m1[c] * k;
        f2[c] = m2[c] * k;
    }
#pragma unroll
    for (int c = 0; c < 8; c++) {
#pragma unroll
        for (int d = c + 1; d < 8; d++) {
            float k = __expf(w * Rs[c * 8 + d]);
            f1[d] += m1[c] * k;  f1[c] += m1[d] * k;
            f2[d] += m2[c] * k;  f2[c] += m2[d] * k;
        }
    }
#pragma unroll
    for (int c = 0; c < 8; c++) {
        lf1[c] = __logf(fmaxf(f1[c], EPS_C)) * en;
        lf2[c] = __logf(fmaxf(f2[c], EPS_C)) * en;
    }
}

// ------------------- first half-iteration: lf & sum from current m ------------
__global__ __launch_bounds__(256) void iterA_k(const int* __restrict__ src,
                                               const int* __restrict__ dst,
                                               __half2* __restrict__ sum_w) {
    __shared__ float Rs[64];
    if (threadIdx.x < 64) Rs[threadIdx.x] = g_Rs[threadIdx.x];
    __syncthreads();
    int e = blockIdx.x * blockDim.x + threadIdx.x;
    if (e >= E2C) return;
    float w = g_w[e], en = g_en[e];
    int s = src[e], d = dst[e];
    float m1[8], m2[8], lf1[8], lf2[8];
    load8h(g_m + (size_t)e * 4, m1);
    load8h(g_m + (size_t)(e + E2C) * 4, m2);
    msg_lf2(Rs, w, m1, m2, en, lf1, lf2);
    store8h(g_lf + (size_t)e * 4, lf1);
    store8h(g_lf + (size_t)(e + E2C) * 4, lf2);
    red8h(sum_w + d * 4, lf1);
    red8h(sum_w + s * 4, lf2);
}

// ------------------- fused BP iteration (update m, then new lf & sum) ---------
__global__ __launch_bounds__(256) void fused_k(const int* __restrict__ src,
                                               const int* __restrict__ dst,
                                               __half2* __restrict__ sum_w) {
    __shared__ float Rs[64];
    if (threadIdx.x < 64) Rs[threadIdx.x] = g_Rs[threadIdx.x];
    __syncthreads();
    int e = blockIdx.x * blockDim.x + threadIdx.x;
    if (e >= E2C) return;
    float alpha = g_alpha;
    int s = src[e], d = dst[e];
    float lf1[8], lf2[8], m1[8], m2[8];
    load8h(g_lf + (size_t)e * 4, lf1);
    load8h(g_lf + (size_t)(e + E2C) * 4, lf2);
    load8h(g_m + (size_t)e * 4, m1);
    load8h(g_m + (size_t)(e + E2C) * 4, m2);
    {
        float bs[8];
        load8h(g_b16 + s * 4, bs);
        upd_m(m1, bs, lf2, alpha);   // dir s->d: t = b[s] - alpha*lf(rev)
    }
    {
        float bd[8];
        load8h(g_b16 + d * 4, bd);
        upd_m(m2, bd, lf1, alpha);   // dir d->s: t = b[d] - alpha*lf1
    }
    store8h(g_m + (size_t)e * 4, m1);
    store8h(g_m + (size_t)(e + E2C) * 4, m2);
    float w = g_w[e], en = g_en[e];
    float nlf1[8], nlf2[8];
    msg_lf2(Rs, w, m1, m2, en, nlf1, nlf2);
    store8h(g_lf + (size_t)e * 4, nlf1);
    store8h(g_lf + (size_t)(e + E2C) * 4, nlf2);
    red8h(sum_w + d * 4, nlf1);
    red8h(sum_w + s * 4, nlf2);
}

// ------------------- final beliefs -------------------------------------------
__global__ void beliefs_k(const __half2* __restrict__ sum_r, float* __restrict__ out) {
    int n = blockIdx.x * blockDim.x + threadIdx.x;
    if (n >= NN) return;
    float alpha = g_alpha;
    float lp[8], si[8];
    load8(g_logphi + n * 8, lp);
    load8h(sum_r + n * 4, si);
    float t[8], mx = -1e30f;
#pragma unroll
    for (int c = 0; c < 8; c++) { t[c] = lp[c] + alpha * si[c]; mx = fmaxf(mx, t[c]); }
    float ex[8], sm = 0.f;
#pragma unroll
    for (int c = 0; c < 8; c++) { ex[c] = expf(t[c] - mx); sm += ex[c]; }
    float inv = 1.f / sm;
    float o[8];
#pragma unroll
    for (int c = 0; c < 8; c++) o[c] = ex[c] * inv;
    store8(out + (size_t)n * 8, o);
}

// ------------------- launcher -------------------------------------------------
extern "C" void kernel_launch(void* const* d_in, const int* in_sizes, int n_in,
                              void* d_out, int out_size) {
    const float* x      = (const float*)d_in[0];
    const int*   ei     = (const int*)  d_in[1];   // [2, E] : row0 src, row1 dst
    const float* enc_w1 = (const float*)d_in[3];
    const float* enc_b1 = (const float*)d_in[4];
    const float* enc_w2 = (const float*)d_in[5];
    const float* enc_b2 = (const float*)d_in[6];
    const float* edge_w1= (const float*)d_in[7];
    const float* edge_b1= (const float*)d_in[8];
    const float* edge_w2= (const float*)d_in[9];
    const float* edge_b2= (const float*)d_in[10];
    const float* R_raw  = (const float*)d_in[11];
    const float* rsl    = (const float*)d_in[12];
    const float* msg    = (const float*)d_in[13];
    float* out = (float*)d_out;

    const int* src = ei;         // first E2 entries of row0 are unique-edge srcs
    const int* dst = ei + EEC;   // row1

    __half2* sumA; cudaGetSymbolAddress((void**)&sumA, g_sum16A);
    __half2* sumB; cudaGetSymbolAddress((void**)&sumB, g_sum16B);

    prep0_k<<<(NN + 255) / 256, 256>>>(R_raw, rsl, msg);
    enc_gemm_k<<<dim3((NN + 127) / 128, HID / 64), 256>>>(x, enc_w1, enc_b1);
    deg_k<<<(E2C + 255) / 256, 256>>>(src, dst);
    edge_mlp_k<<<E2C / 128, 256>>>(src, dst, edge_w1, edge_b1, edge_w2, edge_b2);
    logits_k<<<(NN * 32 + 255) / 256, 256>>>(enc_w2, enc_b2);
    init_m_k<<<(EEC + 255) / 256, 256>>>(src);  // row0 spans all E directed edges

    // zero sumA: NN*4 half2 = 16*NN bytes = NN float4s
    zero4_k<<<(NN + 255) / 256, 256>>>((float4*)sumA, NN);
    iterA_k<<<(E2C + 255) / 256, 256>>>(src, dst, sumA);

    __half2* cur = sumA;
    __half2* nxt = sumB;
    for (int t = 0; t < T_ITERS; t++) {
        node_k<<<(NN + 255) / 256, 256>>>(cur, nxt);   // b16 = lp + a*cur ; nxt = 0
        fused_k<<<(E2C + 255) / 256, 256>>>(src, dst, nxt);
        __half2* tmp = cur; cur = nxt; nxt = tmp;
    }
    beliefs_k<<<(NN + 255) / 256, 256>>>(cur, out);
}

// round 17
// speedup vs baseline: 1.0973x; 1.0163x over previous
#include <cuda_runtime.h>
#include <cuda_fp16.h>
#include <cuda_bf16.h>
#include <math.h>

#define NN      50000
#define INDIM   512
#define HID     256
#define CC      8
#define E2C     400000
#define EEC     800000
#define T_ITERS 10
#define ETA_C   0.2f
#define W_MAXC  0.8f
#define ALPHA_MAXC 1.5f
#define EPS_C   1e-12f

// ------------------- scratch (device globals; no allocation allowed) ---------
__device__ __align__(16) __nv_bfloat162 g_hb[NN * HID / 2]; // 25.6 MB (bf16 h)
__device__ __align__(16) float g_logits[NN * CC];    // fused logits accumulator
__device__ __align__(16) float g_logphi[NN * CC];
__device__ __align__(16) float g_deg[NN];
__device__ __align__(16) float g_w[E2C];
__device__ __align__(16) float g_en[E2C];
__device__ __align__(16) __half2 g_m[EEC * 4];       // 12.8 MB (fp16)
__device__ __align__(16) __half2 g_lf[EEC * 4];      // 12.8 MB (fp16)
__device__ __align__(16) __half2 g_sum16A[NN * 4];   // fp16 sums
__device__ __align__(16) __half2 g_sum16B[NN * 4];
__device__ __align__(16) __half2 g_b16[NN * 4];      // fp16 b = lp + alpha*sum
__device__ __align__(16) float g_Rs[64];
__device__ float g_alpha;

// ------------------- bf16 pack helpers ----------------------------------------
__device__ __forceinline__ unsigned pack_bf16(__nv_bfloat16 lo, __nv_bfloat16 hi) {
    return ((unsigned)__bfloat16_as_ushort(hi) << 16) | __bfloat16_as_ushort(lo);
}
__device__ __forceinline__ unsigned pack_bf16f(float lo, float hi) {
    __nv_bfloat162 t = __floats2bfloat162_rn(lo, hi);
    return *(unsigned*)&t;
}
__device__ __forceinline__ __nv_bfloat162 u2bf(unsigned x) {
    __nv_bfloat162 r; *(unsigned*)&r = x; return r;
}
__device__ __forceinline__ unsigned bf2u(__nv_bfloat162 x) {
    return *(unsigned*)&x;
}

#define MMA_BF16(accp, a0, a1, a2, a3, b0, b1) \
    asm("mma.sync.aligned.m16n8k16.row.col.f32.bf16.bf16.f32 " \
        "{%0,%1,%2,%3}, {%4,%5,%6,%7}, {%8,%9}, {%0,%1,%2,%3};" \
        : "+f"((accp)[0]), "+f"((accp)[1]), "+f"((accp)[2]), "+f"((accp)[3]) \
        : "r"(a0), "r"(a1), "r"(a2), "r"(a3), "r"(b0), "r"(b1))

// ------------------- vector reductions (atomic add, no return) ----------------
__device__ __forceinline__ void red4(float* p, float a, float b, float c, float d) {
    asm volatile("red.global.add.v4.f32 [%0], {%1, %2, %3, %4};"
                 :: "l"(p), "f"(a), "f"(b), "f"(c), "f"(d) : "memory");
}
__device__ __forceinline__ void red8h(__half2* p, const float* v) {
    __half2 h0 = __floats2half2_rn(v[0], v[1]);
    __half2 h1 = __floats2half2_rn(v[2], v[3]);
    __half2 h2 = __floats2half2_rn(v[4], v[5]);
    __half2 h3 = __floats2half2_rn(v[6], v[7]);
    asm volatile("red.global.add.noftz.v4.f16x2 [%0], {%1, %2, %3, %4};"
                 :: "l"(p), "r"(*(unsigned*)&h0), "r"(*(unsigned*)&h1),
                    "r"(*(unsigned*)&h2), "r"(*(unsigned*)&h3) : "memory");
}

// ------------------- generic zero --------------------------------------------
__global__ void zero4_k(float4* __restrict__ p, int n4) {
    int i = blockIdx.x * blockDim.x + threadIdx.x;
    if (i < n4) p[i] = make_float4(0.f, 0.f, 0.f, 0.f);
}

// ------------------- prep: zero deg + symmetrized R + alpha -------------------
__global__ void prep0_k(const float* __restrict__ R_raw,
                        const float* __restrict__ rsl,
                        const float* __restrict__ msg) {
    int i = blockIdx.x * blockDim.x + threadIdx.x;
    if (i < NN) g_deg[i] = 0.f;
    if (blockIdx.x == 0) {
        int t = threadIdx.x;
        if (t == 0) g_alpha = ALPHA_MAXC / (1.f + expf(-msg[0]));
        if (t < 64) {
            int c = t >> 3, d = t & 7;
            float r = 0.5f * (R_raw[c * 8 + d] + R_raw[d * 8 + c]);
            float xr = rsl[0];
            float sp = (xr > 20.f) ? xr : log1pf(expf(xr));
            g_Rs[t] = (sp + 1e-6f) * tanhf(r);
        }
    }
}

// ------------------- encoder GEMM (split-bf16 mma) + fused logits -------------
// h = relu(X @ W1 + b1); writes bf16 h only; accumulates h @ W2 partials
// into g_logits via red4 (logits kernel eliminated).
__global__ __launch_bounds__(256, 3) void enc_gemm_k(const float* __restrict__ X,
                                                     const float* __restrict__ W,
                                                     const float* __restrict__ B,
                                                     const float* __restrict__ W2) {
    __shared__ unsigned Ahi[128][20], Alo[128][20];   // bf16x2 pairs (16/row) pad 20
    __shared__ unsigned Bpk[2][2][8][68];             // [mat][s][rp][n] pad 68
    __shared__ float W2s[64][8];                      // W2 rows for this col block

    int tid  = threadIdx.x;
    int wid  = tid >> 5;
    int lane = tid & 31;
    int gid  = lane >> 2;
    int tg   = lane & 3;
    int warp_m = wid & 3;          // 4 x 32 rows
    int warp_n = wid >> 2;         // 2 x 32 cols
    int row0 = blockIdx.x * 128;
    int col0 = blockIdx.y * 64;

    // load W2 block: rows col0..col0+63, 8 classes each (512 floats = 256 float2)
    {
        float2 v = *(const float2*)(W2 + col0 * 8 + tid * 2);
        ((float2*)W2s)[tid] = v;
    }

    float acc[2][4][4];
#pragma unroll
    for (int mt = 0; mt < 2; mt++)
#pragma unroll
        for (int nt = 0; nt < 4; nt++)
#pragma unroll
            for (int r = 0; r < 4; r++) acc[mt][nt][r] = 0.f;

    for (int f0 = 0; f0 < INDIM; f0 += 32) {
        // ---- stage A: 128 rows x 32 k, hi/lo split, pair-packed ----
#pragma unroll
        for (int i = 0; i < 4; i++) {
            int idx = tid + i * 256;
            int row = idx >> 3;
            int f4  = idx & 7;
            int gr = row0 + row;
            float4 v = make_float4(0.f, 0.f, 0.f, 0.f);
            if (gr < NN) v = *(const float4*)(X + (size_t)gr * INDIM + f0 + f4 * 4);
            __nv_bfloat16 hx = __float2bfloat16(v.x);
            __nv_bfloat16 hy = __float2bfloat16(v.y);
            __nv_bfloat16 hz = __float2bfloat16(v.z);
            __nv_bfloat16 hw = __float2bfloat16(v.w);
            Ahi[row][f4 * 2]     = pack_bf16(hx, hy);
            Ahi[row][f4 * 2 + 1] = pack_bf16(hz, hw);
            Alo[row][f4 * 2]     = pack_bf16f(v.x - __bfloat162float(hx),
                                              v.y - __bfloat162float(hy));
            Alo[row][f4 * 2 + 1] = pack_bf16f(v.z - __bfloat162float(hz),
                                              v.w - __bfloat162float(hw));
        }
        // ---- stage B: 32 k rows x 64 cols of W, hi/lo, pair-packed ----
        {
            int s  = tid >> 7;             // 0..1 (k16 step)
            int rp = (tid >> 4) & 7;       // 0..7 = 2*tg + half
            int n0 = (tid & 15) * 4;
            int k0 = f0 + s * 16 + (rp & 1) * 8 + (rp >> 1) * 2;
            float4 w0 = *(const float4*)(W + (size_t)k0 * HID + col0 + n0);
            float4 w1 = *(const float4*)(W + (size_t)(k0 + 1) * HID + col0 + n0);
            __nv_bfloat16 h00 = __float2bfloat16(w0.x), h10 = __float2bfloat16(w1.x);
            __nv_bfloat16 h01 = __float2bfloat16(w0.y), h11 = __float2bfloat16(w1.y);
            __nv_bfloat16 h02 = __float2bfloat16(w0.z), h12 = __float2bfloat16(w1.z);
            __nv_bfloat16 h03 = __float2bfloat16(w0.w), h13 = __float2bfloat16(w1.w);
            Bpk[0][s][rp][n0 + 0] = pack_bf16(h00, h10);
            Bpk[0][s][rp][n0 + 1] = pack_bf16(h01, h11);
            Bpk[0][s][rp][n0 + 2] = pack_bf16(h02, h12);
            Bpk[0][s][rp][n0 + 3] = pack_bf16(h03, h13);
            Bpk[1][s][rp][n0 + 0] = pack_bf16f(w0.x - __bfloat162float(h00),
                                               w1.x - __bfloat162float(h10));
            Bpk[1][s][rp][n0 + 1] = pack_bf16f(w0.y - __bfloat162float(h01),
                                               w1.y - __bfloat162float(h11));
            Bpk[1][s][rp][n0 + 2] = pack_bf16f(w0.z - __bfloat162float(h02),
                                               w1.z - __bfloat162float(h12));
            Bpk[1][s][rp][n0 + 3] = pack_bf16f(w0.w - __bfloat162float(h03),
                                               w1.w - __bfloat162float(h13));
        }
        __syncthreads();

        // ---- compute: 2 k16 steps ----
#pragma unroll
        for (int s = 0; s < 2; s++) {
            unsigned bh[4][2], bl[4][2];
#pragma unroll
            for (int nt = 0; nt < 4; nt++) {
                int n = warp_n * 32 + nt * 8 + gid;
                bh[nt][0] = Bpk[0][s][2 * tg][n];
                bh[nt][1] = Bpk[0][s][2 * tg + 1][n];
                bl[nt][0] = Bpk[1][s][2 * tg][n];
                bl[nt][1] = Bpk[1][s][2 * tg + 1][n];
            }
#pragma unroll
            for (int mt = 0; mt < 2; mt++) {
                int m = warp_m * 32 + mt * 16;
                unsigned ah0 = Ahi[m + gid][s * 8 + tg];
                unsigned ah1 = Ahi[m + 8 + gid][s * 8 + tg];
                unsigned ah2 = Ahi[m + gid][s * 8 + 4 + tg];
                unsigned ah3 = Ahi[m + 8 + gid][s * 8 + 4 + tg];
                unsigned al0 = Alo[m + gid][s * 8 + tg];
                unsigned al1 = Alo[m + 8 + gid][s * 8 + tg];
                unsigned al2 = Alo[m + gid][s * 8 + 4 + tg];
                unsigned al3 = Alo[m + 8 + gid][s * 8 + 4 + tg];
#pragma unroll
                for (int nt = 0; nt < 4; nt++) {
                    MMA_BF16(acc[mt][nt], ah0, ah1, ah2, ah3, bh[nt][0], bh[nt][1]);
                    MMA_BF16(acc[mt][nt], ah0, ah1, ah2, ah3, bl[nt][0], bl[nt][1]);
                    MMA_BF16(acc[mt][nt], al0, al1, al2, al3, bh[nt][0], bh[nt][1]);
                }
            }
        }
        __syncthreads();
    }

    // ---- epilogue: bias + relu (into acc), bf16 store, fused logits ----
#pragma unroll
    for (int mt = 0; mt < 2; mt++) {
#pragma unroll
        for (int nt = 0; nt < 4; nt++) {
            int col = col0 + warp_n * 32 + nt * 8 + 2 * tg;
            float2 bv = *(const float2*)(B + col);
            acc[mt][nt][0] = fmaxf(acc[mt][nt][0] + bv.x, 0.f);
            acc[mt][nt][1] = fmaxf(acc[mt][nt][1] + bv.y, 0.f);
            acc[mt][nt][2] = fmaxf(acc[mt][nt][2] + bv.x, 0.f);
            acc[mt][nt][3] = fmaxf(acc[mt][nt][3] + bv.y, 0.f);
            int r0 = row0 + warp_m * 32 + mt * 16 + gid;
            if (r0 < NN)
                g_hb[((size_t)r0 * HID + col) >> 1] = __floats2bfloat162_rn(acc[mt][nt][0], acc[mt][nt][1]);
            int r1 = r0 + 8;
            if (r1 < NN)
                g_hb[((size_t)r1 * HID + col) >> 1] = __floats2bfloat162_rn(acc[mt][nt][2], acc[mt][nt][3]);
        }
    }
    // logits partials: each (row, this block's 8 cols per thread) -> h @ W2
#pragma unroll
    for (int mt = 0; mt < 2; mt++) {
#pragma unroll
        for (int rh = 0; rh < 2; rh++) {
            float part[8];
#pragma unroll
            for (int c = 0; c < 8; c++) part[c] = 0.f;
#pragma unroll
            for (int nt = 0; nt < 4; nt++) {
#pragma unroll
                for (int cc = 0; cc < 2; cc++) {
                    int cl = warp_n * 32 + nt * 8 + 2 * tg + cc;
                    float v = acc[mt][nt][rh * 2 + cc];
#pragma unroll
                    for (int c = 0; c < 8; c++) part[c] += v * W2s[cl][c];
                }
            }
#pragma unroll
            for (int c = 0; c < 8; c++) {
                part[c] += __shfl_down_sync(0xffffffffu, part[c], 1, 4);
                part[c] += __shfl_down_sync(0xffffffffu, part[c], 2, 4);
            }
            if (tg == 0) {
                int gr = row0 + warp_m * 32 + mt * 16 + rh * 8 + gid;
                if (gr < NN) {
                    red4(g_logits + gr * 8,     part[0], part[1], part[2], part[3]);
                    red4(g_logits + gr * 8 + 4, part[4], part[5], part[6], part[7]);
                }
            }
        }
    }
}

// ------------------- log_softmax over fused logits ----------------------------
__global__ void logsm_k(const float* __restrict__ B2) {
    int n = blockIdx.x * blockDim.x + threadIdx.x;
    if (n >= NN) return;
    float4 l0 = *(const float4*)(g_logits + n * 8);
    float4 l1 = *(const float4*)(g_logits + n * 8 + 4);
    float lg[8] = {l0.x, l0.y, l0.z, l0.w, l1.x, l1.y, l1.z, l1.w};
    float mx = -1e30f;
#pragma unroll
    for (int c = 0; c < 8; c++) { lg[c] += B2[c]; mx = fmaxf(mx, lg[c]); }
    float s = 0.f;
#pragma unroll
    for (int c = 0; c < 8; c++) s += expf(lg[c] - mx);
    float lse = mx + logf(s);
    *(float4*)(g_logphi + n * 8)     = make_float4(lg[0]-lse, lg[1]-lse, lg[2]-lse, lg[3]-lse);
    *(float4*)(g_logphi + n * 8 + 4) = make_float4(lg[4]-lse, lg[5]-lse, lg[6]-lse, lg[7]-lse);
}

// ------------------- degrees -------------------------------------------------
__global__ void deg_k(const int* __restrict__ src, const int* __restrict__ dst) {
    int e = blockIdx.x * blockDim.x + threadIdx.x;
    if (e >= E2C) return;
    atomicAdd(&g_deg[src[e]], 1.f);
    atomicAdd(&g_deg[dst[e]], 1.f);
}

// ------------------- edge MLP via bf16 mma.sync (m16n8k16) --------------------
__global__ __launch_bounds__(256, 3) void edge_mlp_k(const int* __restrict__ src,
                                                     const int* __restrict__ dst,
                                                     const float* __restrict__ W1,
                                                     const float* __restrict__ B1,
                                                     const float* __restrict__ W2,
                                                     const float* __restrict__ B2) {
    __shared__ int   ss[128], dd[128];
    __shared__ float s0s[128], s1s[128];
    __shared__ unsigned Hsp[128][20], Hdp[128][20];  // bf16x2 pairs, 16/row, pad 20
    __shared__ unsigned Bw[2][2][8][72];             // [part][s][rp][n] bf16x2 pairs
    __shared__ float Wg0[64], Wg1[64], b1s[64], w2s[64];
    __shared__ float wsum[128];

    int tid  = threadIdx.x;
    int wid  = tid >> 5;
    int lane = tid & 31;
    int gid  = lane >> 2;      // group id 0..7
    int tg   = lane & 3;       // thread-in-group 0..3
    int warp_m = wid & 3;      // 4 m-warps * 32 edges
    int warp_n = wid >> 2;     // 2 n-warps * 32 cols
    int e0 = blockIdx.x * 128;

    if (tid < 128) {
        int ge = e0 + tid;
        int s = src[ge], d = dst[ge];
        ss[tid] = s; dd[tid] = d;
        float degs = g_deg[s], degd = g_deg[d];
        float a = logf(degs + 1.f), b = logf(degd + 1.f);
        s0s[tid] = a + b; s1s[tid] = fabsf(a - b);
        float ds = fmaxf(degs, 1.f), dd2 = fmaxf(degd, 1.f);
        g_en[ge] = rsqrtf(ds * dd2);
        wsum[tid] = 0.f;
    } else {
        int t = tid - 128;
        if (t < 64) { Wg0[t] = W1[512 * 64 + t]; b1s[t] = B1[t]; }
        else { int u = t - 64; Wg1[u] = W1[513 * 64 + u]; w2s[u] = W2[u]; }
    }
    __syncthreads();

    float acc[2][4][4];
#pragma unroll
    for (int mt = 0; mt < 2; mt++)
#pragma unroll
        for (int nt = 0; nt < 4; nt++)
#pragma unroll
            for (int r = 0; r < 4; r++) acc[mt][nt][r] = 0.f;

    for (int f0 = 0; f0 < HID; f0 += 32) {
        // ---- stage A: raw bf16x2 copies of hs/hd rows (no conversion) ----
        {
            int e = tid >> 1;
            int half = tid & 1;
            const uint4* hs4 = (const uint4*)(g_hb + (((size_t)ss[e] * HID + f0) >> 1) + half * 8);
            const uint4* hd4 = (const uint4*)(g_hb + (((size_t)dd[e] * HID + f0) >> 1) + half * 8);
#pragma unroll
            for (int j = 0; j < 2; j++) {
                *(uint4*)&Hsp[e][half * 8 + j * 4] = hs4[j];
                *(uint4*)&Hdp[e][half * 8 + j * 4] = hd4[j];
            }
        }
        // ---- stage B: weight k-pairs as bf16x2, both parts ----
        {
            int part = tid >> 7;           // 0..1
            int s    = (tid >> 6) & 1;     // 0..1
            int rp   = (tid >> 3) & 7;     // 0..7: (rp>>2)=khalf, (rp&3)=tg
            int n0   = (tid & 7) * 8;
            int rk = (part ? 256 : 0) + f0 + s * 16 + (rp >> 2) * 8 + (rp & 3) * 2;
            const float* Wp = W1 + (size_t)rk * 64 + n0;
            float4 w0a = *(const float4*)(Wp);
            float4 w0b = *(const float4*)(Wp + 4);
            float4 w1a = *(const float4*)(Wp + 64);
            float4 w1b = *(const float4*)(Wp + 68);
            unsigned* o = &Bw[part][s][rp][n0];
            o[0] = pack_bf16f(w0a.x, w1a.x);
            o[1] = pack_bf16f(w0a.y, w1a.y);
            o[2] = pack_bf16f(w0a.z, w1a.z);
            o[3] = pack_bf16f(w0a.w, w1a.w);
            o[4] = pack_bf16f(w0b.x, w1b.x);
            o[5] = pack_bf16f(w0b.y, w1b.y);
            o[6] = pack_bf16f(w0b.z, w1b.z);
            o[7] = pack_bf16f(w0b.w, w1b.w);
        }
        __syncthreads();

        // ---- compute: 2 k16 steps; P/Q built from one hs/hd load set ----
#pragma unroll
        for (int s = 0; s < 2; s++) {
            unsigned bP[4][2], bQ[4][2];
#pragma unroll
            for (int nt = 0; nt < 4; nt++) {
                int n = warp_n * 32 + nt * 8 + gid;
                bP[nt][0] = Bw[0][s][tg][n];
                bP[nt][1] = Bw[0][s][4 + tg][n];
                bQ[nt][0] = Bw[1][s][tg][n];
                bQ[nt][1] = Bw[1][s][4 + tg][n];
            }
#pragma unroll
            for (int mt = 0; mt < 2; mt++) {
                int m = warp_m * 32 + mt * 16;
                __nv_bfloat162 hs0 = u2bf(Hsp[m + gid][s * 8 + tg]);
                __nv_bfloat162 hs1 = u2bf(Hsp[m + 8 + gid][s * 8 + tg]);
                __nv_bfloat162 hs2 = u2bf(Hsp[m + gid][s * 8 + 4 + tg]);
                __nv_bfloat162 hs3 = u2bf(Hsp[m + 8 + gid][s * 8 + 4 + tg]);
                __nv_bfloat162 hd0 = u2bf(Hdp[m + gid][s * 8 + tg]);
                __nv_bfloat162 hd1 = u2bf(Hdp[m + 8 + gid][s * 8 + tg]);
                __nv_bfloat162 hd2 = u2bf(Hdp[m + gid][s * 8 + 4 + tg]);
                __nv_bfloat162 hd3 = u2bf(Hdp[m + 8 + gid][s * 8 + 4 + tg]);
                unsigned p0 = bf2u(__hmul2(hs0, hd0));
                unsigned p1 = bf2u(__hmul2(hs1, hd1));
                unsigned p2 = bf2u(__hmul2(hs2, hd2));
                unsigned p3 = bf2u(__hmul2(hs3, hd3));
                unsigned q0 = bf2u(__habs2(__hsub2(hs0, hd0)));
                unsigned q1 = bf2u(__habs2(__hsub2(hs1, hd1)));
                unsigned q2 = bf2u(__habs2(__hsub2(hs2, hd2)));
                unsigned q3 = bf2u(__habs2(__hsub2(hs3, hd3)));
#pragma unroll
                for (int nt = 0; nt < 4; nt++) {
                    MMA_BF16(acc[mt][nt], p0, p1, p2, p3, bP[nt][0], bP[nt][1]);
                    MMA_BF16(acc[mt][nt], q0, q1, q2, q3, bQ[nt][0], bQ[nt][1]);
                }
            }
        }
        __syncthreads();
    }

    // ---- epilogue: struct feats + bias + relu + w2 dot, reduce into wsum ----
#pragma unroll
    for (int mt = 0; mt < 2; mt++) {
#pragma unroll
        for (int rh = 0; rh < 2; rh++) {
            int e = warp_m * 32 + mt * 16 + rh * 8 + gid;
            float s0 = s0s[e], s1 = s1s[e];
            float partial = 0.f;
#pragma unroll
            for (int nt = 0; nt < 4; nt++) {
#pragma unroll
                for (int cc = 0; cc < 2; cc++) {
                    int u = warp_n * 32 + nt * 8 + 2 * tg + cc;
                    float v = acc[mt][nt][rh * 2 + cc];
                    v += s0 * Wg0[u] + s1 * Wg1[u] + b1s[u];
                    v = fmaxf(v, 0.f);
                    partial += v * w2s[u];
                }
            }
            atomicAdd(&wsum[e], partial);
        }
    }
    __syncthreads();
    if (tid < 128) {
        float wr = wsum[tid] + B2[0];
        g_w[e0 + tid] = W_MAXC / (1.f + expf(-wr));
    }
}

// ------------------- fp16 row helpers ----------------------------------------
__device__ __forceinline__ void load8h(const __half2* p, float* r) {
    uint4 v = *(const uint4*)p;
    float2 f0 = __half22float2(*(__half2*)&v.x);
    float2 f1 = __half22float2(*(__half2*)&v.y);
    float2 f2 = __half22float2(*(__half2*)&v.z);
    float2 f3 = __half22float2(*(__half2*)&v.w);
    r[0]=f0.x; r[1]=f0.y; r[2]=f1.x; r[3]=f1.y;
    r[4]=f2.x; r[5]=f2.y; r[6]=f3.x; r[7]=f3.y;
}
__device__ __forceinline__ void store8h(__half2* p, const float* r) {
    uint4 v;
    __half2 h0 = __floats2half2_rn(r[0], r[1]);
    __half2 h1 = __floats2half2_rn(r[2], r[3]);
    __half2 h2 = __floats2half2_rn(r[4], r[5]);
    __half2 h3 = __floats2half2_rn(r[6], r[7]);
    v.x = *(unsigned*)&h0; v.y = *(unsigned*)&h1;
    v.z = *(unsigned*)&h2; v.w = *(unsigned*)&h3;
    *(uint4*)p = v;
}
__device__ __forceinline__ void load8(const float* p, float* r) {
    float4 v0 = *(const float4*)p;
    float4 v1 = *(const float4*)(p + 4);
    r[0]=v0.x; r[1]=v0.y; r[2]=v0.z; r[3]=v0.w;
    r[4]=v1.x; r[5]=v1.y; r[6]=v1.z; r[7]=v1.w;
}
__device__ __forceinline__ void store8(float* p, const float* r) {
    *(float4*)p       = make_float4(r[0], r[1], r[2], r[3]);
    *(float4*)(p + 4) = make_float4(r[4], r[5], r[6], r[7]);
}

// ------------------- init m = softmax(log_phi[src]) over all E edges ----------
__global__ void init_m_k(const int* __restrict__ srcAll) {
    int e = blockIdx.x * blockDim.x + threadIdx.x;
    if (e >= EEC) return;
    int s = srcAll[e];
    float lp[8];
    load8(g_logphi + s * 8, lp);
    float mx = -1e30f;
#pragma unroll
    for (int c = 0; c < 8; c++) mx = fmaxf(mx, lp[c]);
    float ex[8], sm = 0.f;
#pragma unroll
    for (int c = 0; c < 8; c++) { ex[c] = expf(lp[c] - mx); sm += ex[c]; }
    float inv = 1.f / sm;
    float o[8];
#pragma unroll
    for (int c = 0; c < 8; c++) o[c] = ex[c] * inv;
    store8h(g_m + (size_t)e * 4, o);
}

// ------------------- node kernel: b16 = lp + alpha*sum_cur; zero sum_nxt ------
__global__ void node_k(const __half2* __restrict__ sum_cur,
                       __half2* __restrict__ sum_nxt) {
    int n = blockIdx.x * blockDim.x + threadIdx.x;
    if (n >= NN) return;
    float alpha = g_alpha;
    float lp[8], si[8], b[8];
    load8(g_logphi + n * 8, lp);
    load8h(sum_cur + n * 4, si);
#pragma unroll
    for (int c = 0; c < 8; c++) b[c] = lp[c] + alpha * si[c];
    store8h(g_b16 + n * 4, b);
    uint4 z = make_uint4(0u, 0u, 0u, 0u);
    *(uint4*)(sum_nxt + n * 4) = z;
}

// ------------------- BP core helpers -----------------------------------------
__device__ __forceinline__ void upd_m(float* mrow, const float* b,
                                      const float* lf_rev, float alpha) {
    float t[8], mx = -1e30f;
#pragma unroll
    for (int c = 0; c < 8; c++) { t[c] = b[c] - alpha * lf_rev[c]; mx = fmaxf(mx, t[c]); }
    float ex[8], sm = 0.f;
#pragma unroll
    for (int c = 0; c < 8; c++) { ex[c] = __expf(t[c] - mx); sm += ex[c]; }
    float inv = 1.f / sm;
    float m[8], tot = 0.f;
#pragma unroll
    for (int c = 0; c < 8; c++) {
        m[c] = (1.f - ETA_C) * mrow[c] + ETA_C * (ex[c] * inv);
        m[c] = fmaxf(m[c], EPS_C);
        tot += m[c];
    }
    float it = 1.f / tot;
#pragma unroll
    for (int c = 0; c < 8; c++) mrow[c] = m[c] * it;
}
// K = exp(w*R) is symmetric (R symmetric): 36 distinct exps, shared by both
// directions. f1 = m1 K, f2 = m2 K, then lf = log(max(f, eps)) * en.
__device__ __forceinline__ void msg_lf2(const float* Rs, float w,
                                        const float* m1, const float* m2,
                                        float en, float* lf1, float* lf2) {
    float f1[8], f2[8];
#pragma unroll
    for (int c = 0; c < 8; c++) {
        float k = __expf(w * Rs[c * 9]);        // diagonal
        f1[c] = m1[c] * k;
        f2[c] = m2[c] * k;
    }
#pragma unroll
    for (int c = 0; c < 8; c++) {
#pragma unroll
        for (int d = c + 1; d < 8; d++) {
            float k = __expf(w * Rs[c * 8 + d]);
            f1[d] += m1[c] * k;  f1[c] += m1[d] * k;
            f2[d] += m2[c] * k;  f2[c] += m2[d] * k;
        }
    }
#pragma unroll
    for (int c = 0; c < 8; c++) {
        lf1[c] = __logf(fmaxf(f1[c], EPS_C)) * en;
        lf2[c] = __logf(fmaxf(f2[c], EPS_C)) * en;
    }
}

// ------------------- first half-iteration: lf & sum from current m ------------
__global__ __launch_bounds__(256) void iterA_k(const int* __restrict__ src,
                                               const int* __restrict__ dst,
                                               __half2* __restrict__ sum_w) {
    __shared__ float Rs[64];
    if (threadIdx.x < 64) Rs[threadIdx.x] = g_Rs[threadIdx.x];
    __syncthreads();
    int e = blockIdx.x * blockDim.x + threadIdx.x;
    if (e >= E2C) return;
    float w = g_w[e], en = g_en[e];
    int s = src[e], d = dst[e];
    float m1[8], m2[8], lf1[8], lf2[8];
    load8h(g_m + (size_t)e * 4, m1);
    load8h(g_m + (size_t)(e + E2C) * 4, m2);
    msg_lf2(Rs, w, m1, m2, en, lf1, lf2);
    store8h(g_lf + (size_t)e * 4, lf1);
    store8h(g_lf + (size_t)(e + E2C) * 4, lf2);
    red8h(sum_w + d * 4, lf1);
    red8h(sum_w + s * 4, lf2);
}

// ------------------- fused BP iteration (update m, then new lf & sum) ---------
__global__ __launch_bounds__(256) void fused_k(const int* __restrict__ src,
                                               const int* __restrict__ dst,
                                               __half2* __restrict__ sum_w) {
    __shared__ float Rs[64];
    if (threadIdx.x < 64) Rs[threadIdx.x] = g_Rs[threadIdx.x];
    __syncthreads();
    int e = blockIdx.x * blockDim.x + threadIdx.x;
    if (e >= E2C) return;
    float alpha = g_alpha;
    int s = src[e], d = dst[e];
    float lf1[8], lf2[8], m1[8], m2[8];
    load8h(g_lf + (size_t)e * 4, lf1);
    load8h(g_lf + (size_t)(e + E2C) * 4, lf2);
    load8h(g_m + (size_t)e * 4, m1);
    load8h(g_m + (size_t)(e + E2C) * 4, m2);
    {
        float bs[8];
        load8h(g_b16 + s * 4, bs);
        upd_m(m1, bs, lf2, alpha);   // dir s->d: t = b[s] - alpha*lf(rev)
    }
    {
        float bd[8];
        load8h(g_b16 + d * 4, bd);
        upd_m(m2, bd, lf1, alpha);   // dir d->s: t = b[d] - alpha*lf1
    }
    store8h(g_m + (size_t)e * 4, m1);
    store8h(g_m + (size_t)(e + E2C) * 4, m2);
    float w = g_w[e], en = g_en[e];
    float nlf1[8], nlf2[8];
    msg_lf2(Rs, w, m1, m2, en, nlf1, nlf2);
    store8h(g_lf + (size_t)e * 4, nlf1);
    store8h(g_lf + (size_t)(e + E2C) * 4, nlf2);
    red8h(sum_w + d * 4, nlf1);
    red8h(sum_w + s * 4, nlf2);
}

// ------------------- final beliefs -------------------------------------------
__global__ void beliefs_k(const __half2* __restrict__ sum_r, float* __restrict__ out) {
    int n = blockIdx.x * blockDim.x + threadIdx.x;
    if (n >= NN) return;
    float alpha = g_alpha;
    float lp[8], si[8];
    load8(g_logphi + n * 8, lp);
    load8h(sum_r + n * 4, si);
    float t[8], mx = -1e30f;
#pragma unroll
    for (int c = 0; c < 8; c++) { t[c] = lp[c] + alpha * si[c]; mx = fmaxf(mx, t[c]); }
    float ex[8], sm = 0.f;
#pragma unroll
    for (int c = 0; c < 8; c++) { ex[c] = expf(t[c] - mx); sm += ex[c]; }
    float inv = 1.f / sm;
    float o[8];
#pragma unroll
    for (int c = 0; c < 8; c++) o[c] = ex[c] * inv;
    store8(out + (size_t)n * 8, o);
}

// ------------------- launcher -------------------------------------------------
extern "C" void kernel_launch(void* const* d_in, const int* in_sizes, int n_in,
                              void* d_out, int out_size) {
    const float* x      = (const float*)d_in[0];
    const int*   ei     = (const int*)  d_in[1];   // [2, E] : row0 src, row1 dst
    const float* enc_w1 = (const float*)d_in[3];
    const float* enc_b1 = (const float*)d_in[4];
    const float* enc_w2 = (const float*)d_in[5];
    const float* enc_b2 = (const float*)d_in[6];
    const float* edge_w1= (const float*)d_in[7];
    const float* edge_b1= (const float*)d_in[8];
    const float* edge_w2= (const float*)d_in[9];
    const float* edge_b2= (const float*)d_in[10];
    const float* R_raw  = (const float*)d_in[11];
    const float* rsl    = (const float*)d_in[12];
    const float* msg    = (const float*)d_in[13];
    float* out = (float*)d_out;

    const int* src = ei;         // first E2 entries of row0 are unique-edge srcs
    const int* dst = ei + EEC;   // row1

    __half2* sumA; cudaGetSymbolAddress((void**)&sumA, g_sum16A);
    __half2* sumB; cudaGetSymbolAddress((void**)&sumB, g_sum16B);
    float* logitsP; cudaGetSymbolAddress((void**)&logitsP, g_logits);

    prep0_k<<<(NN + 255) / 256, 256>>>(R_raw, rsl, msg);
    zero4_k<<<(NN * 2 + 255) / 256, 256>>>((float4*)logitsP, NN * 2);
    enc_gemm_k<<<dim3((NN + 127) / 128, HID / 64), 256>>>(x, enc_w1, enc_b1, enc_w2);
    deg_k<<<(E2C + 255) / 256, 256>>>(src, dst);
    edge_mlp_k<<<E2C / 128, 256>>>(src, dst, edge_w1, edge_b1, edge_w2, edge_b2);
    logsm_k<<<(NN + 255) / 256, 256>>>(enc_b2);
    init_m_k<<<(EEC + 255) / 256, 256>>>(src);  // row0 spans all E directed edges

    // zero sumA: NN*4 half2 = 16*NN bytes = NN float4s
    zero4_k<<<(NN + 255) / 256, 256>>>((float4*)sumA, NN);
    iterA_k<<<(E2C + 255) / 256, 256>>>(src, dst, sumA);

    __half2* cur = sumA;
    __half2* nxt = sumB;
    for (int t = 0; t < T_ITERS; t++) {
        node_k<<<(NN + 255) / 256, 256>>>(cur, nxt);   // b16 = lp + a*cur ; nxt = 0
        fused_k<<<(E2C + 255) / 256, 256>>>(src, dst, nxt);
        __half2* tmp = cur; cur = nxt; nxt = tmp;
    }
    beliefs_k<<<(NN + 255) / 256, 256>>>(cur, out);
}